// round 2
// baseline (speedup 1.0000x reference)
#include <cuda_runtime.h>
#include <math.h>

// ---------------------------------------------------------------------------
// Scratch (device globals; no allocation in kernel_launch)
// ---------------------------------------------------------------------------
__device__ float g_tiles[4096 * 1024];        // (4096 imgs, 32, 32)
__device__ float g_p1[4096 * 32 * 225];       // (4096, 32, 15, 15)
__device__ float g_p2[4096 * 32 * 36];        // (4096, 32, 36)
__device__ float g_u[4096 * 2048];            // (4096*32, 64) == (16,32,256,64)
__device__ float g_x[4096 * 2048];            // encoder input (4096, 2048)
__device__ float g_qkv[4096 * 6144];
__device__ float g_att[4096 * 2048];
__device__ float g_tmp[4096 * 2048];
__device__ float g_x1[4096 * 2048];
__device__ float g_h2[4096 * 2048];
__device__ float g_x2[4096 * 2048];
__device__ float g_f1p[32 * 256 * 512];       // split-K partials
__device__ float g_f1o[256 * 512];
__device__ float g_f2o[256 * 128];

// ---------------------------------------------------------------------------
// 1) tile + /255
// ---------------------------------------------------------------------------
__global__ void k_tile(const float* __restrict__ t) {
    int img = blockIdx.x;                 // b*16 + r4*4 + c4
    int b = img >> 4, tile = img & 15;
    int r4 = tile >> 2, c4 = tile & 3;
    const float* src = t + b * 16384 + (r4 * 32) * 128 + c4 * 32;
    float* dst = g_tiles + img * 1024;
    for (int i = threadIdx.x; i < 1024; i += 256) {
        int r = i >> 5, c = i & 31;
        dst[i] = src[r * 128 + c] * (1.0f / 255.0f);
    }
}

// ---------------------------------------------------------------------------
// 2) conv1 (1->32, 3x3 VALID) + maxpool 2x2  -> (4096,32,15,15)
// ---------------------------------------------------------------------------
__global__ void k_conv1(const float* __restrict__ w, const float* __restrict__ bias) {
    __shared__ float sim[1024];
    __shared__ float sw[288];
    __shared__ float sb[32];
    int img = blockIdx.x;
    int tid = threadIdx.x;                // 256
    for (int i = tid; i < 1024; i += 256) sim[i] = g_tiles[img * 1024 + i];
    for (int i = tid; i < 288; i += 256) sw[i] = w[i];   // FIX: strided (288 > 256)
    if (tid < 32) sb[tid] = bias[tid];
    __syncthreads();
    if (tid >= 225) return;
    int oi = tid / 15, oj = tid % 15;
    float p[4][4];
#pragma unroll
    for (int r = 0; r < 4; r++)
#pragma unroll
        for (int c = 0; c < 4; c++)
            p[r][c] = sim[(2 * oi + r) * 32 + (2 * oj + c)];
    float* o = g_p1 + img * 7200 + tid;
#pragma unroll 4
    for (int oc = 0; oc < 32; oc++) {
        float a0 = 0.f, a1 = 0.f, a2 = 0.f, a3 = 0.f;
#pragma unroll
        for (int ky = 0; ky < 3; ky++)
#pragma unroll
            for (int kx = 0; kx < 3; kx++) {
                float wv = sw[oc * 9 + ky * 3 + kx];
                a0 = fmaf(p[ky][kx], wv, a0);
                a1 = fmaf(p[ky][kx + 1], wv, a1);
                a2 = fmaf(p[ky + 1][kx], wv, a2);
                a3 = fmaf(p[ky + 1][kx + 1], wv, a3);
            }
        o[oc * 225] = fmaxf(fmaxf(a0, a1), fmaxf(a2, a3)) + sb[oc];
    }
}

// ---------------------------------------------------------------------------
// 3) conv2 (32->32, 3x3 VALID) + maxpool 2x2 -> (4096,32,6,6)
//    dynamic smem: input image 7200 + weights 9216 floats = 65664 B
// ---------------------------------------------------------------------------
__global__ void k_conv2(const float* __restrict__ w, const float* __restrict__ bias) {
    extern __shared__ float sm2[];
    float* sin = sm2;            // 7200
    float* sw  = sm2 + 7200;     // 9216
    __shared__ float sb[32];
    int img = blockIdx.x;
    int tid = threadIdx.x;       // 256
    for (int i = tid; i < 7200; i += 256) sin[i] = g_p1[img * 7200 + i];
    for (int i = tid; i < 9216; i += 256) sw[i] = w[i];
    if (tid < 32) sb[tid] = bias[tid];
    __syncthreads();
    for (int idx = tid; idx < 1152; idx += 256) {
        int oc = idx / 36, pos = idx % 36;
        int oi = pos / 6, oj = pos % 6;
        int y0 = 2 * oi, x0 = 2 * oj;
        float a0 = 0.f, a1 = 0.f, a2 = 0.f, a3 = 0.f;
        const float* wp = sw + oc * 288;
        for (int ic = 0; ic < 32; ic++) {
            const float* ip = sin + ic * 225 + y0 * 15 + x0;
            float p[4][4];
#pragma unroll
            for (int r = 0; r < 4; r++)
#pragma unroll
                for (int c = 0; c < 4; c++) p[r][c] = ip[r * 15 + c];
#pragma unroll
            for (int ky = 0; ky < 3; ky++)
#pragma unroll
                for (int kx = 0; kx < 3; kx++) {
                    float wv = wp[ic * 9 + ky * 3 + kx];
                    a0 = fmaf(p[ky][kx], wv, a0);
                    a1 = fmaf(p[ky][kx + 1], wv, a1);
                    a2 = fmaf(p[ky + 1][kx], wv, a2);
                    a3 = fmaf(p[ky + 1][kx + 1], wv, a3);
                }
        }
        g_p2[img * 1152 + idx] = fmaxf(fmaxf(a0, a1), fmaxf(a2, a3)) + sb[oc];
    }
}

// ---------------------------------------------------------------------------
// 4) expand: relu( (131072,36) @ (64,36)^T + b ) -> (131072,64)
// ---------------------------------------------------------------------------
__global__ void k_expand(const float* __restrict__ w, const float* __restrict__ bias) {
    __shared__ float sw[64 * 36];   // transposed [d][e]
    __shared__ float sb[64];
    __shared__ float srow[4 * 36];
    int tid = threadIdx.x;          // 256
    for (int i = tid; i < 2304; i += 256) {
        int e = i / 36, d = i % 36;
        sw[d * 64 + e] = w[i];
    }
    if (tid < 64) sb[tid] = bias[tid];
    int row0 = blockIdx.x * 4;
    if (tid < 144) srow[tid] = g_p2[row0 * 36 + tid];
    __syncthreads();
    int r = tid >> 6, c = tid & 63;
    float acc = sb[c];
#pragma unroll
    for (int d = 0; d < 36; d++) acc = fmaf(srow[r * 36 + d], sw[d * 64 + c], acc);
    g_u[(row0 + r) * 64 + c] = fmaxf(acc, 0.0f);
}

// ---------------------------------------------------------------------------
// 5) grouped MHA (G=16,L=32,B=256,E=64,h=4) + residual + LN(64) -> g_x
//    one block per (g,b), 192 threads; dyn smem 58112 B
// ---------------------------------------------------------------------------
__global__ void k_gattn(const float* __restrict__ wqkv, const float* __restrict__ bqkv,
                        const float* __restrict__ wo, const float* __restrict__ bo,
                        const float* __restrict__ lnw, const float* __restrict__ lnb) {
    extern __shared__ float sm5[];
    float* su   = sm5;            // 32 x 64            (2048)
    float* sqkv = sm5 + 2048;     // 32 rows, stride 193 (6176)
    float* ssc  = sm5 + 8224;     // 128 rows, stride 33 (4224)
    float* so   = sm5 + 12448;    // 32 rows, stride 65  (2080)
    float* sy   = sm5 + 2048;     // reuse sqkv region, 32x64

    int g = blockIdx.x >> 8, b = blockIdx.x & 255;
    int tid = threadIdx.x;        // 192

    for (int i = tid; i < 2048; i += 192) {
        int l = i >> 6, e = i & 63;
        su[i] = g_u[((g * 32 + l) * 256 + b) * 64 + e];
    }
    __syncthreads();

    // qkv: thread = output feature e' in [0,192)
    {
        const float* W = wqkv + (g * 192 + tid) * 64;
        float acc[32];
        float bq = bqkv[g * 192 + tid];
#pragma unroll
        for (int l = 0; l < 32; l++) acc[l] = bq;
        for (int d = 0; d < 64; d++) {
            float wv = __ldg(W + d);
#pragma unroll
            for (int l = 0; l < 32; l++) acc[l] = fmaf(su[l * 64 + d], wv, acc[l]);
        }
#pragma unroll
        for (int l = 0; l < 32; l++) sqkv[l * 193 + tid] = acc[l];
    }
    __syncthreads();

    // scores + softmax: thread = (h,i) for tid<128
    if (tid < 128) {
        int h = tid >> 5, i = tid & 31;
        float s[32];
        float mx = -1e30f;
        for (int j = 0; j < 32; j++) {
            float acc = 0.f;
#pragma unroll
            for (int d = 0; d < 16; d++)
                acc = fmaf(sqkv[i * 193 + h * 16 + d], sqkv[j * 193 + 64 + h * 16 + d], acc);
            acc *= 0.25f;                    // hd^-0.5, hd=16
            s[j] = acc;
            mx = fmaxf(mx, acc);
        }
        float sum = 0.f;
        for (int j = 0; j < 32; j++) { s[j] = __expf(s[j] - mx); sum += s[j]; }
        float inv = 1.0f / sum;
        for (int j = 0; j < 32; j++) ssc[(h * 32 + i) * 33 + j] = s[j] * inv;
    }
    __syncthreads();

    // o = att @ v
    if (tid < 128) {
        int h = tid >> 5, i = tid & 31;
        float acc[16];
#pragma unroll
        for (int d = 0; d < 16; d++) acc[d] = 0.f;
        for (int j = 0; j < 32; j++) {
            float a = ssc[(h * 32 + i) * 33 + j];
#pragma unroll
            for (int d = 0; d < 16; d++)
                acc[d] = fmaf(a, sqkv[j * 193 + 128 + h * 16 + d], acc[d]);
        }
#pragma unroll
        for (int d = 0; d < 16; d++) so[i * 65 + h * 16 + d] = acc[d];
    }
    __syncthreads();

    // out-proj + residual into sy (overwrites sqkv region)
    for (int idx = tid; idx < 2048; idx += 192) {
        int l = idx >> 6, oo = idx & 63;
        const float* W = wo + g * 4096 + oo * 64;
        float acc = bo[g * 64 + oo];
#pragma unroll 8
        for (int e = 0; e < 64; e++) acc = fmaf(so[l * 65 + e], __ldg(W + e), acc);
        sy[idx] = acc + su[idx];
    }
    __syncthreads();

    // LN over 64, warp per row
    int warp = tid >> 5, lane = tid & 31;
    for (int l = warp; l < 32; l += 6) {
        float v0 = sy[l * 64 + lane], v1 = sy[l * 64 + 32 + lane];
        float s = v0 + v1, s2 = v0 * v0 + v1 * v1;
#pragma unroll
        for (int o = 16; o; o >>= 1) {
            s += __shfl_xor_sync(0xffffffffu, s, o);
            s2 += __shfl_xor_sync(0xffffffffu, s2, o);
        }
        float mu = s * (1.0f / 64.0f);
        float var = s2 * (1.0f / 64.0f) - mu * mu;
        float inv = rsqrtf(var + 1e-5f);
        int base = ((g * 32 + l) * 256 + b) * 64;
        g_x[base + lane]      = (v0 - mu) * inv * lnw[lane] + lnb[lane];
        g_x[base + 32 + lane] = (v1 - mu) * inv * lnw[32 + lane] + lnb[32 + lane];
    }
}

// ---------------------------------------------------------------------------
// SGEMM: C = A(M,K) @ B(N,K)^T (+bias, optional relu). 128x128x16 tile,
// 256 threads, 8x8 microtile. Supports split-K via blockIdx.z.
// ---------------------------------------------------------------------------
template <bool RELU>
__global__ __launch_bounds__(256, 2)
void sgemm128(const float* __restrict__ A, const float* __restrict__ B,
              const float* __restrict__ bias, float* __restrict__ C,
              int M, int N, int K, int kChunk, int partStride) {
    __shared__ float As[16][132];
    __shared__ float Bs[16][132];
    const int tid = threadIdx.x;
    const int m0 = blockIdx.y * 128;
    const int n0 = blockIdx.x * 128;
    const int ks = blockIdx.z * kChunk;
    float* Cp = C + (size_t)blockIdx.z * partStride;

    const int lr = tid >> 2;         // 0..63
    const int lk = (tid & 3) * 4;    // 0,4,8,12
    const float* Aptr = A + (size_t)(m0 + lr) * K + ks + lk;
    const float* Bptr = B + (size_t)(n0 + lr) * K + ks + lk;

    const int ty = tid >> 4, tx = tid & 15;

    float acc[8][8];
#pragma unroll
    for (int i = 0; i < 8; i++)
#pragma unroll
        for (int j = 0; j < 8; j++) acc[i][j] = 0.f;

    for (int kt = 0; kt < kChunk; kt += 16) {
        float4 a0 = *(const float4*)(Aptr + kt);
        float4 a1 = *(const float4*)(Aptr + (size_t)64 * K + kt);
        float4 b0 = *(const float4*)(Bptr + kt);
        float4 b1 = *(const float4*)(Bptr + (size_t)64 * K + kt);
        __syncthreads();
        As[lk + 0][lr] = a0.x; As[lk + 1][lr] = a0.y; As[lk + 2][lr] = a0.z; As[lk + 3][lr] = a0.w;
        As[lk + 0][lr + 64] = a1.x; As[lk + 1][lr + 64] = a1.y; As[lk + 2][lr + 64] = a1.z; As[lk + 3][lr + 64] = a1.w;
        Bs[lk + 0][lr] = b0.x; Bs[lk + 1][lr] = b0.y; Bs[lk + 2][lr] = b0.z; Bs[lk + 3][lr] = b0.w;
        Bs[lk + 0][lr + 64] = b1.x; Bs[lk + 1][lr + 64] = b1.y; Bs[lk + 2][lr + 64] = b1.z; Bs[lk + 3][lr + 64] = b1.w;
        __syncthreads();
#pragma unroll
        for (int kk = 0; kk < 16; kk++) {
            float a[8], bb[8];
            *(float4*)(a)     = *(const float4*)&As[kk][ty * 8];
            *(float4*)(a + 4) = *(const float4*)&As[kk][ty * 8 + 4];
            *(float4*)(bb)     = *(const float4*)&Bs[kk][tx * 8];
            *(float4*)(bb + 4) = *(const float4*)&Bs[kk][tx * 8 + 4];
#pragma unroll
            for (int i = 0; i < 8; i++)
#pragma unroll
                for (int j = 0; j < 8; j++) acc[i][j] = fmaf(a[i], bb[j], acc[i][j]);
        }
    }

#pragma unroll
    for (int i = 0; i < 8; i++) {
        int m = m0 + ty * 8 + i;
        float* cp = Cp + (size_t)m * N + n0 + tx * 8;
#pragma unroll
        for (int j = 0; j < 8; j++) {
            float v = acc[i][j];
            if (bias) v += bias[n0 + tx * 8 + j];
            if (RELU) v = fmaxf(v, 0.f);
            cp[j] = v;
        }
    }
}

// ---------------------------------------------------------------------------
// encoder attention: one block per (b,h); L=16, hd=128
// ---------------------------------------------------------------------------
__global__ void k_encattn() {
    __shared__ float sq[16 * 128];
    __shared__ float sk[16 * 129];
    __shared__ float sv[16 * 129];
    __shared__ float ss[16 * 16];
    int b = blockIdx.x >> 4, h = blockIdx.x & 15;
    int tid = threadIdx.x;   // 128
    const float scale = 0.08838834764831845f;  // 128^-0.5
    for (int i = tid; i < 2048; i += 128) {
        int l = i >> 7, d = i & 127;
        int base = (l * 256 + b) * 6144 + h * 128 + d;
        sq[l * 128 + d] = g_qkv[base] * scale;
        sk[l * 129 + d] = g_qkv[base + 2048];
        sv[l * 129 + d] = g_qkv[base + 4096];
    }
    __syncthreads();
    for (int idx = tid; idx < 256; idx += 128) {
        int i = idx >> 4, j = idx & 15;
        float acc = 0.f;
#pragma unroll 8
        for (int d = 0; d < 128; d++) acc = fmaf(sq[i * 128 + d], sk[j * 129 + d], acc);
        ss[idx] = acc;
    }
    __syncthreads();
    if (tid < 16) {
        float mx = -1e30f;
        for (int j = 0; j < 16; j++) mx = fmaxf(mx, ss[tid * 16 + j]);
        float sum = 0.f;
        for (int j = 0; j < 16; j++) { float e = __expf(ss[tid * 16 + j] - mx); ss[tid * 16 + j] = e; sum += e; }
        float inv = 1.0f / sum;
        for (int j = 0; j < 16; j++) ss[tid * 16 + j] *= inv;
    }
    __syncthreads();
    for (int idx = tid; idx < 2048; idx += 128) {
        int i = idx >> 7, d = idx & 127;
        float acc = 0.f;
#pragma unroll
        for (int j = 0; j < 16; j++) acc = fmaf(ss[i * 16 + j], sv[j * 129 + d], acc);
        g_att[(i * 256 + b) * 2048 + h * 128 + d] = acc;
    }
}

// ---------------------------------------------------------------------------
// LayerNorm over 2048: out = LN(x + r) * w + b   (block per row)
// ---------------------------------------------------------------------------
__global__ void k_ln2048(const float* __restrict__ x, const float* __restrict__ r,
                         const float* __restrict__ w, const float* __restrict__ b,
                         float* __restrict__ out) {
    int row = blockIdx.x, tid = threadIdx.x;   // 256
    const float* xp = x + (size_t)row * 2048;
    const float* rp = r + (size_t)row * 2048;
    float v[8];
    float s = 0.f, s2 = 0.f;
#pragma unroll
    for (int i = 0; i < 8; i++) {
        float t = xp[tid + i * 256] + rp[tid + i * 256];
        v[i] = t; s += t; s2 += t * t;
    }
    __shared__ float sh[64];
#pragma unroll
    for (int o = 16; o; o >>= 1) {
        s += __shfl_xor_sync(0xffffffffu, s, o);
        s2 += __shfl_xor_sync(0xffffffffu, s2, o);
    }
    int warp = tid >> 5, lane = tid & 31;
    if (lane == 0) { sh[warp] = s; sh[32 + warp] = s2; }
    __syncthreads();
    if (warp == 0) {
        s = (lane < 8) ? sh[lane] : 0.f;
        s2 = (lane < 8) ? sh[32 + lane] : 0.f;
#pragma unroll
        for (int o = 4; o; o >>= 1) {
            s += __shfl_xor_sync(0xffffffffu, s, o);
            s2 += __shfl_xor_sync(0xffffffffu, s2, o);
        }
        if (lane == 0) { sh[0] = s; sh[1] = s2; }
    }
    __syncthreads();
    float mu = sh[0] * (1.0f / 2048.0f);
    float var = sh[1] * (1.0f / 2048.0f) - mu * mu;
    float inv = rsqrtf(var + 1e-5f);
#pragma unroll
    for (int i = 0; i < 8; i++) {
        int c = tid + i * 256;
        out[(size_t)row * 2048 + c] = (v[i] - mu) * inv * w[c] + b[c];
    }
}

// ---------------------------------------------------------------------------
// f1 split-K reduce + bias + relu
// ---------------------------------------------------------------------------
__global__ void k_f1red(const float* __restrict__ bias) {
    int idx = blockIdx.x * 256 + threadIdx.x;   // < 131072
    float s = bias[idx & 511];
#pragma unroll
    for (int z = 0; z < 32; z++) s += g_f1p[z * 131072 + idx];
    g_f1o[idx] = fmaxf(s, 0.f);
}

__global__ void k_f2(const float* __restrict__ w, const float* __restrict__ bias) {
    __shared__ float srow[512];
    int b = blockIdx.x, tid = threadIdx.x;   // 128
    for (int i = tid; i < 512; i += 128) srow[i] = g_f1o[b * 512 + i];
    __syncthreads();
    float acc = bias[tid];
    const float* wp = w + tid * 512;
#pragma unroll 8
    for (int d = 0; d < 512; d++) acc = fmaf(srow[d], __ldg(wp + d), acc);
    g_f2o[b * 128 + tid] = fmaxf(acc, 0.f);
}

__global__ void k_f3(const float* __restrict__ w, const float* __restrict__ bias,
                     float* __restrict__ out) {
    __shared__ float srow[128];
    int b = blockIdx.x, tid = threadIdx.x;   // 32
    for (int i = tid; i < 128; i += 32) srow[i] = g_f2o[b * 128 + i];
    __syncthreads();
    if (tid < 25) {
        float acc = bias[tid];
        const float* wp = w + tid * 128;
#pragma unroll
        for (int d = 0; d < 128; d++) acc = fmaf(srow[d], wp[d], acc);
        out[b * 25 + tid] = acc;
    }
}

// ---------------------------------------------------------------------------
// launch
// ---------------------------------------------------------------------------
extern "C" void kernel_launch(void* const* d_in, const int* in_sizes, int n_in,
                              void* d_out, int out_size) {
    const float* t        = (const float*)d_in[0];
    const float* conv1_w  = (const float*)d_in[1];
    const float* conv1_b  = (const float*)d_in[2];
    const float* conv2_w  = (const float*)d_in[3];
    const float* conv2_b  = (const float*)d_in[4];
    const float* expand_w = (const float*)d_in[5];
    const float* expand_b = (const float*)d_in[6];
    const float* mha_wqkv = (const float*)d_in[7];
    const float* mha_bqkv = (const float*)d_in[8];
    const float* mha_wo   = (const float*)d_in[9];
    const float* mha_bo   = (const float*)d_in[10];
    const float* ln1_w    = (const float*)d_in[11];
    const float* ln1_b    = (const float*)d_in[12];
    const float* enc_wqkv = (const float*)d_in[13];
    const float* enc_bqkv = (const float*)d_in[14];
    const float* enc_wo   = (const float*)d_in[15];
    const float* enc_bo   = (const float*)d_in[16];
    const float* enc_ln1w = (const float*)d_in[17];
    const float* enc_ln1b = (const float*)d_in[18];
    const float* enc_w1   = (const float*)d_in[19];
    const float* enc_b1   = (const float*)d_in[20];
    const float* enc_w2   = (const float*)d_in[21];
    const float* enc_b2   = (const float*)d_in[22];
    const float* enc_ln2w = (const float*)d_in[23];
    const float* enc_ln2b = (const float*)d_in[24];
    const float* f1_w     = (const float*)d_in[25];
    const float* f1_b     = (const float*)d_in[26];
    const float* f2_w     = (const float*)d_in[27];
    const float* f2_b     = (const float*)d_in[28];
    const float* f3_w     = (const float*)d_in[29];
    const float* f3_b     = (const float*)d_in[30];
    float* out = (float*)d_out;

    cudaFuncSetAttribute(k_conv2, cudaFuncAttributeMaxDynamicSharedMemorySize, 65664);
    cudaFuncSetAttribute(k_gattn, cudaFuncAttributeMaxDynamicSharedMemorySize, 58112);

    float *p_x, *p_qkv, *p_att, *p_tmp, *p_x1, *p_h2, *p_x2, *p_f1p;
    cudaGetSymbolAddress((void**)&p_x,   g_x);
    cudaGetSymbolAddress((void**)&p_qkv, g_qkv);
    cudaGetSymbolAddress((void**)&p_att, g_att);
    cudaGetSymbolAddress((void**)&p_tmp, g_tmp);
    cudaGetSymbolAddress((void**)&p_x1,  g_x1);
    cudaGetSymbolAddress((void**)&p_h2,  g_h2);
    cudaGetSymbolAddress((void**)&p_x2,  g_x2);
    cudaGetSymbolAddress((void**)&p_f1p, g_f1p);

    k_tile<<<4096, 256>>>(t);
    k_conv1<<<4096, 256>>>(conv1_w, conv1_b);
    k_conv2<<<4096, 256, 65664>>>(conv2_w, conv2_b);
    k_expand<<<32768, 256>>>(expand_w, expand_b);
    k_gattn<<<4096, 192, 58112>>>(mha_wqkv, mha_bqkv, mha_wo, mha_bo, ln1_w, ln1_b);

    // encoder qkv: (4096,2048) @ (6144,2048)^T
    sgemm128<false><<<dim3(48, 32, 1), 256>>>(p_x, enc_wqkv, enc_bqkv, p_qkv,
                                              4096, 6144, 2048, 2048, 0);
    k_encattn<<<4096, 128>>>();
    // out proj
    sgemm128<false><<<dim3(16, 32, 1), 256>>>(p_att, enc_wo, enc_bo, p_tmp,
                                              4096, 2048, 2048, 2048, 0);
    k_ln2048<<<4096, 256>>>(p_x, p_tmp, enc_ln1w, enc_ln1b, p_x1);
    // FFN
    sgemm128<true><<<dim3(16, 32, 1), 256>>>(p_x1, enc_w1, enc_b1, p_h2,
                                             4096, 2048, 2048, 2048, 0);
    sgemm128<false><<<dim3(16, 32, 1), 256>>>(p_h2, enc_w2, enc_b2, p_tmp,
                                              4096, 2048, 2048, 2048, 0);
    k_ln2048<<<4096, 256>>>(p_x1, p_tmp, enc_ln2w, enc_ln2b, p_x2);

    // f1: (256,32768) @ (512,32768)^T, split-K 32
    sgemm128<false><<<dim3(4, 2, 32), 256>>>(p_x2, f1_w, nullptr, p_f1p,
                                             256, 512, 32768, 1024, 256 * 512);
    k_f1red<<<512, 256>>>(f1_b);
    k_f2<<<256, 128>>>(f2_w, f2_b);
    k_f3<<<256, 32>>>(f3_w, f3_b, out);
}

// round 3
// speedup vs baseline: 1.0006x; 1.0006x over previous
#include <cuda_runtime.h>
#include <math.h>

// ---------------------------------------------------------------------------
// Scratch (device globals; no allocation in kernel_launch)
// ---------------------------------------------------------------------------
__device__ float g_tiles[4096 * 1024];        // (4096 imgs, 32, 32)
__device__ float g_p1[4096 * 32 * 225];       // (4096, 32, 15, 15)
__device__ float g_p2[4096 * 32 * 36];        // (4096, 32, 36)
__device__ float g_u[4096 * 2048];            // (4096*32, 64) == (16,32,256,64)
__device__ float g_x[4096 * 2048];            // encoder input (4096, 2048)
__device__ float g_qkv[4096 * 6144];
__device__ float g_att[4096 * 2048];
__device__ float g_tmp[4096 * 2048];
__device__ float g_x1[4096 * 2048];
__device__ float g_h2[4096 * 2048];
__device__ float g_x2[4096 * 2048];
__device__ float g_f1p[32 * 256 * 512];       // split-K partials
__device__ float g_f1o[256 * 512];
__device__ float g_f2o[256 * 128];

// ---------------------------------------------------------------------------
// 1) tile + /255
// ---------------------------------------------------------------------------
__global__ void k_tile(const float* __restrict__ t) {
    int img = blockIdx.x;                 // b*16 + r4*4 + c4
    int b = img >> 4, tile = img & 15;
    int r4 = tile >> 2, c4 = tile & 3;
    const float* src = t + b * 16384 + (r4 * 32) * 128 + c4 * 32;
    float* dst = g_tiles + img * 1024;
    for (int i = threadIdx.x; i < 1024; i += 256) {
        int r = i >> 5, c = i & 31;
        dst[i] = src[r * 128 + c] * (1.0f / 255.0f);
    }
}

// ---------------------------------------------------------------------------
// 2) conv1 (1->32, 3x3 VALID) + maxpool 2x2  -> (4096,32,15,15)
// ---------------------------------------------------------------------------
__global__ void k_conv1(const float* __restrict__ w, const float* __restrict__ bias) {
    __shared__ float sim[1024];
    __shared__ float sw[288];
    __shared__ float sb[32];
    int img = blockIdx.x;
    int tid = threadIdx.x;                // 256
    for (int i = tid; i < 1024; i += 256) sim[i] = g_tiles[img * 1024 + i];
    for (int i = tid; i < 288; i += 256) sw[i] = w[i];   // FIX: strided (288 > 256)
    if (tid < 32) sb[tid] = bias[tid];
    __syncthreads();
    if (tid >= 225) return;
    int oi = tid / 15, oj = tid % 15;
    float p[4][4];
#pragma unroll
    for (int r = 0; r < 4; r++)
#pragma unroll
        for (int c = 0; c < 4; c++)
            p[r][c] = sim[(2 * oi + r) * 32 + (2 * oj + c)];
    float* o = g_p1 + img * 7200 + tid;
#pragma unroll 4
    for (int oc = 0; oc < 32; oc++) {
        float a0 = 0.f, a1 = 0.f, a2 = 0.f, a3 = 0.f;
#pragma unroll
        for (int ky = 0; ky < 3; ky++)
#pragma unroll
            for (int kx = 0; kx < 3; kx++) {
                float wv = sw[oc * 9 + ky * 3 + kx];
                a0 = fmaf(p[ky][kx], wv, a0);
                a1 = fmaf(p[ky][kx + 1], wv, a1);
                a2 = fmaf(p[ky + 1][kx], wv, a2);
                a3 = fmaf(p[ky + 1][kx + 1], wv, a3);
            }
        o[oc * 225] = fmaxf(fmaxf(a0, a1), fmaxf(a2, a3)) + sb[oc];
    }
}

// ---------------------------------------------------------------------------
// 3) conv2 (32->32, 3x3 VALID) + maxpool 2x2 -> (4096,32,6,6)
//    dynamic smem: input image 7200 + weights 9216 floats = 65664 B
// ---------------------------------------------------------------------------
__global__ void k_conv2(const float* __restrict__ w, const float* __restrict__ bias) {
    extern __shared__ float sm2[];
    float* sin = sm2;            // 7200
    float* sw  = sm2 + 7200;     // 9216
    __shared__ float sb[32];
    int img = blockIdx.x;
    int tid = threadIdx.x;       // 256
    for (int i = tid; i < 7200; i += 256) sin[i] = g_p1[img * 7200 + i];
    for (int i = tid; i < 9216; i += 256) sw[i] = w[i];
    if (tid < 32) sb[tid] = bias[tid];
    __syncthreads();
    for (int idx = tid; idx < 1152; idx += 256) {
        int oc = idx / 36, pos = idx % 36;
        int oi = pos / 6, oj = pos % 6;
        int y0 = 2 * oi, x0 = 2 * oj;
        float a0 = 0.f, a1 = 0.f, a2 = 0.f, a3 = 0.f;
        const float* wp = sw + oc * 288;
        for (int ic = 0; ic < 32; ic++) {
            const float* ip = sin + ic * 225 + y0 * 15 + x0;
            float p[4][4];
#pragma unroll
            for (int r = 0; r < 4; r++)
#pragma unroll
                for (int c = 0; c < 4; c++) p[r][c] = ip[r * 15 + c];
#pragma unroll
            for (int ky = 0; ky < 3; ky++)
#pragma unroll
                for (int kx = 0; kx < 3; kx++) {
                    float wv = wp[ic * 9 + ky * 3 + kx];
                    a0 = fmaf(p[ky][kx], wv, a0);
                    a1 = fmaf(p[ky][kx + 1], wv, a1);
                    a2 = fmaf(p[ky + 1][kx], wv, a2);
                    a3 = fmaf(p[ky + 1][kx + 1], wv, a3);
                }
        }
        g_p2[img * 1152 + idx] = fmaxf(fmaxf(a0, a1), fmaxf(a2, a3)) + sb[oc];
    }
}

// ---------------------------------------------------------------------------
// 4) expand: relu( (131072,36) @ (64,36)^T + b ) -> (131072,64)
// ---------------------------------------------------------------------------
__global__ void k_expand(const float* __restrict__ w, const float* __restrict__ bias) {
    __shared__ float sw[64 * 36];   // transposed [d][e]
    __shared__ float sb[64];
    __shared__ float srow[4 * 36];
    int tid = threadIdx.x;          // 256
    for (int i = tid; i < 2304; i += 256) {
        int e = i / 36, d = i % 36;
        sw[d * 64 + e] = w[i];
    }
    if (tid < 64) sb[tid] = bias[tid];
    int row0 = blockIdx.x * 4;
    if (tid < 144) srow[tid] = g_p2[row0 * 36 + tid];
    __syncthreads();
    int r = tid >> 6, c = tid & 63;
    float acc = sb[c];
#pragma unroll
    for (int d = 0; d < 36; d++) acc = fmaf(srow[r * 36 + d], sw[d * 64 + c], acc);
    g_u[(row0 + r) * 64 + c] = fmaxf(acc, 0.0f);
}

// ---------------------------------------------------------------------------
// 5) grouped MHA (G=16,L=32,B=256,E=64,h=4) + residual + LN(64) -> g_x
//    one block per (g,b), 192 threads; dyn smem 58112 B
// ---------------------------------------------------------------------------
__global__ void k_gattn(const float* __restrict__ wqkv, const float* __restrict__ bqkv,
                        const float* __restrict__ wo, const float* __restrict__ bo,
                        const float* __restrict__ lnw, const float* __restrict__ lnb) {
    extern __shared__ float sm5[];
    float* su   = sm5;            // 32 x 64            (2048)
    float* sqkv = sm5 + 2048;     // 32 rows, stride 193 (6176)
    float* ssc  = sm5 + 8224;     // 128 rows, stride 33 (4224)
    float* so   = sm5 + 12448;    // 32 rows, stride 65  (2080)
    float* sy   = sm5 + 2048;     // reuse sqkv region, 32x64

    int g = blockIdx.x >> 8, b = blockIdx.x & 255;
    int tid = threadIdx.x;        // 192

    for (int i = tid; i < 2048; i += 192) {
        int l = i >> 6, e = i & 63;
        su[i] = g_u[((g * 32 + l) * 256 + b) * 64 + e];
    }
    __syncthreads();

    // qkv: thread = output feature e' in [0,192)
    {
        const float* W = wqkv + (g * 192 + tid) * 64;
        float acc[32];
        float bq = bqkv[g * 192 + tid];
#pragma unroll
        for (int l = 0; l < 32; l++) acc[l] = bq;
        for (int d = 0; d < 64; d++) {
            float wv = __ldg(W + d);
#pragma unroll
            for (int l = 0; l < 32; l++) acc[l] = fmaf(su[l * 64 + d], wv, acc[l]);
        }
#pragma unroll
        for (int l = 0; l < 32; l++) sqkv[l * 193 + tid] = acc[l];
    }
    __syncthreads();

    // scores + softmax: thread = (h,i) for tid<128
    if (tid < 128) {
        int h = tid >> 5, i = tid & 31;
        float s[32];
        float mx = -1e30f;
        for (int j = 0; j < 32; j++) {
            float acc = 0.f;
#pragma unroll
            for (int d = 0; d < 16; d++)
                acc = fmaf(sqkv[i * 193 + h * 16 + d], sqkv[j * 193 + 64 + h * 16 + d], acc);
            acc *= 0.25f;                    // hd^-0.5, hd=16
            s[j] = acc;
            mx = fmaxf(mx, acc);
        }
        float sum = 0.f;
        for (int j = 0; j < 32; j++) { s[j] = __expf(s[j] - mx); sum += s[j]; }
        float inv = 1.0f / sum;
        for (int j = 0; j < 32; j++) ssc[(h * 32 + i) * 33 + j] = s[j] * inv;
    }
    __syncthreads();

    // o = att @ v
    if (tid < 128) {
        int h = tid >> 5, i = tid & 31;
        float acc[16];
#pragma unroll
        for (int d = 0; d < 16; d++) acc[d] = 0.f;
        for (int j = 0; j < 32; j++) {
            float a = ssc[(h * 32 + i) * 33 + j];
#pragma unroll
            for (int d = 0; d < 16; d++)
                acc[d] = fmaf(a, sqkv[j * 193 + 128 + h * 16 + d], acc[d]);
        }
#pragma unroll
        for (int d = 0; d < 16; d++) so[i * 65 + h * 16 + d] = acc[d];
    }
    __syncthreads();

    // out-proj + residual into sy (overwrites sqkv region)
    for (int idx = tid; idx < 2048; idx += 192) {
        int l = idx >> 6, oo = idx & 63;
        const float* W = wo + g * 4096 + oo * 64;
        float acc = bo[g * 64 + oo];
#pragma unroll 8
        for (int e = 0; e < 64; e++) acc = fmaf(so[l * 65 + e], __ldg(W + e), acc);
        sy[idx] = acc + su[idx];
    }
    __syncthreads();

    // LN over 64, warp per row
    int warp = tid >> 5, lane = tid & 31;
    for (int l = warp; l < 32; l += 6) {
        float v0 = sy[l * 64 + lane], v1 = sy[l * 64 + 32 + lane];
        float s = v0 + v1, s2 = v0 * v0 + v1 * v1;
#pragma unroll
        for (int o = 16; o; o >>= 1) {
            s += __shfl_xor_sync(0xffffffffu, s, o);
            s2 += __shfl_xor_sync(0xffffffffu, s2, o);
        }
        float mu = s * (1.0f / 64.0f);
        float var = s2 * (1.0f / 64.0f) - mu * mu;
        float inv = rsqrtf(var + 1e-5f);
        int base = ((g * 32 + l) * 256 + b) * 64;
        g_x[base + lane]      = (v0 - mu) * inv * lnw[lane] + lnb[lane];
        g_x[base + 32 + lane] = (v1 - mu) * inv * lnw[32 + lane] + lnb[32 + lane];
    }
}

// ---------------------------------------------------------------------------
// SGEMM: C = A(M,K) @ B(N,K)^T (+bias, optional relu). 128x128x16 tile,
// 256 threads, 8x8 microtile. Supports split-K via blockIdx.z.
// ---------------------------------------------------------------------------
template <bool RELU>
__global__ __launch_bounds__(256, 2)
void sgemm128(const float* __restrict__ A, const float* __restrict__ B,
              const float* __restrict__ bias, float* __restrict__ C,
              int M, int N, int K, int kChunk, int partStride) {
    __shared__ float As[16][132];
    __shared__ float Bs[16][132];
    const int tid = threadIdx.x;
    const int m0 = blockIdx.y * 128;
    const int n0 = blockIdx.x * 128;
    const int ks = blockIdx.z * kChunk;
    float* Cp = C + (size_t)blockIdx.z * partStride;

    const int lr = tid >> 2;         // 0..63
    const int lk = (tid & 3) * 4;    // 0,4,8,12
    const float* Aptr = A + (size_t)(m0 + lr) * K + ks + lk;
    const float* Bptr = B + (size_t)(n0 + lr) * K + ks + lk;

    const int ty = tid >> 4, tx = tid & 15;

    float acc[8][8];
#pragma unroll
    for (int i = 0; i < 8; i++)
#pragma unroll
        for (int j = 0; j < 8; j++) acc[i][j] = 0.f;

    for (int kt = 0; kt < kChunk; kt += 16) {
        float4 a0 = *(const float4*)(Aptr + kt);
        float4 a1 = *(const float4*)(Aptr + (size_t)64 * K + kt);
        float4 b0 = *(const float4*)(Bptr + kt);
        float4 b1 = *(const float4*)(Bptr + (size_t)64 * K + kt);
        __syncthreads();
        As[lk + 0][lr] = a0.x; As[lk + 1][lr] = a0.y; As[lk + 2][lr] = a0.z; As[lk + 3][lr] = a0.w;
        As[lk + 0][lr + 64] = a1.x; As[lk + 1][lr + 64] = a1.y; As[lk + 2][lr + 64] = a1.z; As[lk + 3][lr + 64] = a1.w;
        Bs[lk + 0][lr] = b0.x; Bs[lk + 1][lr] = b0.y; Bs[lk + 2][lr] = b0.z; Bs[lk + 3][lr] = b0.w;
        Bs[lk + 0][lr + 64] = b1.x; Bs[lk + 1][lr + 64] = b1.y; Bs[lk + 2][lr + 64] = b1.z; Bs[lk + 3][lr + 64] = b1.w;
        __syncthreads();
#pragma unroll
        for (int kk = 0; kk < 16; kk++) {
            float a[8], bb[8];
            *(float4*)(a)     = *(const float4*)&As[kk][ty * 8];
            *(float4*)(a + 4) = *(const float4*)&As[kk][ty * 8 + 4];
            *(float4*)(bb)     = *(const float4*)&Bs[kk][tx * 8];
            *(float4*)(bb + 4) = *(const float4*)&Bs[kk][tx * 8 + 4];
#pragma unroll
            for (int i = 0; i < 8; i++)
#pragma unroll
                for (int j = 0; j < 8; j++) acc[i][j] = fmaf(a[i], bb[j], acc[i][j]);
        }
    }

#pragma unroll
    for (int i = 0; i < 8; i++) {
        int m = m0 + ty * 8 + i;
        float* cp = Cp + (size_t)m * N + n0 + tx * 8;
#pragma unroll
        for (int j = 0; j < 8; j++) {
            float v = acc[i][j];
            if (bias) v += bias[n0 + tx * 8 + j];
            if (RELU) v = fmaxf(v, 0.f);
            cp[j] = v;
        }
    }
}

// ---------------------------------------------------------------------------
// encoder attention: one block per (b,h); L=16, hd=128
// ---------------------------------------------------------------------------
__global__ void k_encattn() {
    __shared__ float sq[16 * 128];
    __shared__ float sk[16 * 129];
    __shared__ float sv[16 * 129];
    __shared__ float ss[16 * 16];
    int b = blockIdx.x >> 4, h = blockIdx.x & 15;
    int tid = threadIdx.x;   // 128
    const float scale = 0.08838834764831845f;  // 128^-0.5
    for (int i = tid; i < 2048; i += 128) {
        int l = i >> 7, d = i & 127;
        int base = (l * 256 + b) * 6144 + h * 128 + d;
        sq[l * 128 + d] = g_qkv[base] * scale;
        sk[l * 129 + d] = g_qkv[base + 2048];
        sv[l * 129 + d] = g_qkv[base + 4096];
    }
    __syncthreads();
    for (int idx = tid; idx < 256; idx += 128) {
        int i = idx >> 4, j = idx & 15;
        float acc = 0.f;
#pragma unroll 8
        for (int d = 0; d < 128; d++) acc = fmaf(sq[i * 128 + d], sk[j * 129 + d], acc);
        ss[idx] = acc;
    }
    __syncthreads();
    if (tid < 16) {
        float mx = -1e30f;
        for (int j = 0; j < 16; j++) mx = fmaxf(mx, ss[tid * 16 + j]);
        float sum = 0.f;
        for (int j = 0; j < 16; j++) { float e = __expf(ss[tid * 16 + j] - mx); ss[tid * 16 + j] = e; sum += e; }
        float inv = 1.0f / sum;
        for (int j = 0; j < 16; j++) ss[tid * 16 + j] *= inv;
    }
    __syncthreads();
    for (int idx = tid; idx < 2048; idx += 128) {
        int i = idx >> 7, d = idx & 127;
        float acc = 0.f;
#pragma unroll
        for (int j = 0; j < 16; j++) acc = fmaf(ss[i * 16 + j], sv[j * 129 + d], acc);
        g_att[(i * 256 + b) * 2048 + h * 128 + d] = acc;
    }
}

// ---------------------------------------------------------------------------
// LayerNorm over 2048: out = LN(x + r) * w + b   (block per row)
// ---------------------------------------------------------------------------
__global__ void k_ln2048(const float* __restrict__ x, const float* __restrict__ r,
                         const float* __restrict__ w, const float* __restrict__ b,
                         float* __restrict__ out) {
    int row = blockIdx.x, tid = threadIdx.x;   // 256
    const float* xp = x + (size_t)row * 2048;
    const float* rp = r + (size_t)row * 2048;
    float v[8];
    float s = 0.f, s2 = 0.f;
#pragma unroll
    for (int i = 0; i < 8; i++) {
        float t = xp[tid + i * 256] + rp[tid + i * 256];
        v[i] = t; s += t; s2 += t * t;
    }
    __shared__ float sh[64];
#pragma unroll
    for (int o = 16; o; o >>= 1) {
        s += __shfl_xor_sync(0xffffffffu, s, o);
        s2 += __shfl_xor_sync(0xffffffffu, s2, o);
    }
    int warp = tid >> 5, lane = tid & 31;
    if (lane == 0) { sh[warp] = s; sh[32 + warp] = s2; }
    __syncthreads();
    if (warp == 0) {
        s = (lane < 8) ? sh[lane] : 0.f;
        s2 = (lane < 8) ? sh[32 + lane] : 0.f;
#pragma unroll
        for (int o = 4; o; o >>= 1) {
            s += __shfl_xor_sync(0xffffffffu, s, o);
            s2 += __shfl_xor_sync(0xffffffffu, s2, o);
        }
        if (lane == 0) { sh[0] = s; sh[1] = s2; }
    }
    __syncthreads();
    float mu = sh[0] * (1.0f / 2048.0f);
    float var = sh[1] * (1.0f / 2048.0f) - mu * mu;
    float inv = rsqrtf(var + 1e-5f);
#pragma unroll
    for (int i = 0; i < 8; i++) {
        int c = tid + i * 256;
        out[(size_t)row * 2048 + c] = (v[i] - mu) * inv * w[c] + b[c];
    }
}

// ---------------------------------------------------------------------------
// f1 split-K reduce + bias + relu
// ---------------------------------------------------------------------------
__global__ void k_f1red(const float* __restrict__ bias) {
    int idx = blockIdx.x * 256 + threadIdx.x;   // < 131072
    float s = bias[idx & 511];
#pragma unroll
    for (int z = 0; z < 32; z++) s += g_f1p[z * 131072 + idx];
    g_f1o[idx] = fmaxf(s, 0.f);
}

__global__ void k_f2(const float* __restrict__ w, const float* __restrict__ bias) {
    __shared__ float srow[512];
    int b = blockIdx.x, tid = threadIdx.x;   // 128
    for (int i = tid; i < 512; i += 128) srow[i] = g_f1o[b * 512 + i];
    __syncthreads();
    float acc = bias[tid];
    const float* wp = w + tid * 512;
#pragma unroll 8
    for (int d = 0; d < 512; d++) acc = fmaf(srow[d], __ldg(wp + d), acc);
    g_f2o[b * 128 + tid] = fmaxf(acc, 0.f);
}

__global__ void k_f3(const float* __restrict__ w, const float* __restrict__ bias,
                     float* __restrict__ out) {
    __shared__ float srow[128];
    int b = blockIdx.x, tid = threadIdx.x;   // 32
    for (int i = tid; i < 128; i += 32) srow[i] = g_f2o[b * 128 + i];
    __syncthreads();
    if (tid < 25) {
        float acc = bias[tid];
        const float* wp = w + tid * 128;
#pragma unroll
        for (int d = 0; d < 128; d++) acc = fmaf(srow[d], wp[d], acc);
        out[b * 25 + tid] = acc;
    }
}

// ---------------------------------------------------------------------------
// launch
// ---------------------------------------------------------------------------
extern "C" void kernel_launch(void* const* d_in, const int* in_sizes, int n_in,
                              void* d_out, int out_size) {
    const float* t        = (const float*)d_in[0];
    const float* conv1_w  = (const float*)d_in[1];
    const float* conv1_b  = (const float*)d_in[2];
    const float* conv2_w  = (const float*)d_in[3];
    const float* conv2_b  = (const float*)d_in[4];
    const float* expand_w = (const float*)d_in[5];
    const float* expand_b = (const float*)d_in[6];
    const float* mha_wqkv = (const float*)d_in[7];
    const float* mha_bqkv = (const float*)d_in[8];
    const float* mha_wo   = (const float*)d_in[9];
    const float* mha_bo   = (const float*)d_in[10];
    const float* ln1_w    = (const float*)d_in[11];
    const float* ln1_b    = (const float*)d_in[12];
    const float* enc_wqkv = (const float*)d_in[13];
    const float* enc_bqkv = (const float*)d_in[14];
    const float* enc_wo   = (const float*)d_in[15];
    const float* enc_bo   = (const float*)d_in[16];
    const float* enc_ln1w = (const float*)d_in[17];
    const float* enc_ln1b = (const float*)d_in[18];
    const float* enc_w1   = (const float*)d_in[19];
    const float* enc_b1   = (const float*)d_in[20];
    const float* enc_w2   = (const float*)d_in[21];
    const float* enc_b2   = (const float*)d_in[22];
    const float* enc_ln2w = (const float*)d_in[23];
    const float* enc_ln2b = (const float*)d_in[24];
    const float* f1_w     = (const float*)d_in[25];
    const float* f1_b     = (const float*)d_in[26];
    const float* f2_w     = (const float*)d_in[27];
    const float* f2_b     = (const float*)d_in[28];
    const float* f3_w     = (const float*)d_in[29];
    const float* f3_b     = (const float*)d_in[30];
    float* out = (float*)d_out;

    cudaFuncSetAttribute(k_conv2, cudaFuncAttributeMaxDynamicSharedMemorySize, 65664);
    cudaFuncSetAttribute(k_gattn, cudaFuncAttributeMaxDynamicSharedMemorySize, 58112);

    float *p_x, *p_qkv, *p_att, *p_tmp, *p_x1, *p_h2, *p_x2, *p_f1p;
    cudaGetSymbolAddress((void**)&p_x,   g_x);
    cudaGetSymbolAddress((void**)&p_qkv, g_qkv);
    cudaGetSymbolAddress((void**)&p_att, g_att);
    cudaGetSymbolAddress((void**)&p_tmp, g_tmp);
    cudaGetSymbolAddress((void**)&p_x1,  g_x1);
    cudaGetSymbolAddress((void**)&p_h2,  g_h2);
    cudaGetSymbolAddress((void**)&p_x2,  g_x2);
    cudaGetSymbolAddress((void**)&p_f1p, g_f1p);

    k_tile<<<4096, 256>>>(t);
    k_conv1<<<4096, 256>>>(conv1_w, conv1_b);
    k_conv2<<<4096, 256, 65664>>>(conv2_w, conv2_b);
    k_expand<<<32768, 256>>>(expand_w, expand_b);
    k_gattn<<<4096, 192, 58112>>>(mha_wqkv, mha_bqkv, mha_wo, mha_bo, ln1_w, ln1_b);

    // encoder qkv: (4096,2048) @ (6144,2048)^T
    sgemm128<false><<<dim3(48, 32, 1), 256>>>(p_x, enc_wqkv, enc_bqkv, p_qkv,
                                              4096, 6144, 2048, 2048, 0);
    k_encattn<<<4096, 128>>>();
    // out proj
    sgemm128<false><<<dim3(16, 32, 1), 256>>>(p_att, enc_wo, enc_bo, p_tmp,
                                              4096, 2048, 2048, 2048, 0);
    k_ln2048<<<4096, 256>>>(p_x, p_tmp, enc_ln1w, enc_ln1b, p_x1);
    // FFN
    sgemm128<true><<<dim3(16, 32, 1), 256>>>(p_x1, enc_w1, enc_b1, p_h2,
                                             4096, 2048, 2048, 2048, 0);
    sgemm128<false><<<dim3(16, 32, 1), 256>>>(p_h2, enc_w2, enc_b2, p_tmp,
                                              4096, 2048, 2048, 2048, 0);
    k_ln2048<<<4096, 256>>>(p_x1, p_tmp, enc_ln2w, enc_ln2b, p_x2);

    // f1: (256,32768) @ (512,32768)^T, split-K 32
    sgemm128<false><<<dim3(4, 2, 32), 256>>>(p_x2, f1_w, nullptr, p_f1p,
                                             256, 512, 32768, 1024, 256 * 512);
    k_f1red<<<512, 256>>>(f1_b);
    k_f2<<<256, 128>>>(f2_w, f2_b);
    k_f3<<<256, 32>>>(f3_w, f3_b, out);
}

// round 5
// speedup vs baseline: 1.2967x; 1.2959x over previous
#include <cuda_runtime.h>
#include <cuda_fp16.h>
#include <math.h>
#include <stdint.h>

// ---------------------------------------------------------------------------
// Scratch
// ---------------------------------------------------------------------------
__device__ float g_tiles[4096 * 1024];
__device__ float g_p1[4096 * 32 * 225];
__device__ float g_p2[4096 * 32 * 36];
__device__ float g_u[4096 * 2048];
__device__ float g_x[4096 * 2048];
__device__ float g_qkv[4096 * 6144];
__device__ float g_att[4096 * 2048];
__device__ float g_tmp[4096 * 2048];
__device__ float g_x1[4096 * 2048];
__device__ float g_h2[4096 * 2048];
__device__ float g_x2[4096 * 2048];
__device__ float g_f1p[32 * 256 * 512];
__device__ float g_f1o[256 * 512];
__device__ float g_f2o[256 * 128];

// ---------------------------------------------------------------------------
// mma.sync m16n8k16 fp16 -> fp32  (baseline PTX, works on plain sm_103)
// ---------------------------------------------------------------------------
__device__ __forceinline__ void mma16816(float* c, const uint32_t* a, const uint32_t* b) {
    asm volatile(
        "mma.sync.aligned.m16n8k16.row.col.f32.f16.f16.f32 "
        "{%0,%1,%2,%3}, {%4,%5,%6,%7}, {%8,%9}, {%0,%1,%2,%3};"
        : "+f"(c[0]), "+f"(c[1]), "+f"(c[2]), "+f"(c[3])
        : "r"(a[0]), "r"(a[1]), "r"(a[2]), "r"(a[3]), "r"(b[0]), "r"(b[1]));
}

// fp32x4 -> fp16 hi (rounded) + fp16 lo (rounded residual)
__device__ __forceinline__ void split4(float4 v, __half2& h0, __half2& h1,
                                       __half2& l0, __half2& l1) {
    __half hx = __float2half_rn(v.x), hy = __float2half_rn(v.y);
    __half hz = __float2half_rn(v.z), hw = __float2half_rn(v.w);
    h0 = __halves2half2(hx, hy);
    h1 = __halves2half2(hz, hw);
    float lx = v.x - __half2float(hx), ly = v.y - __half2float(hy);
    float lz = v.z - __half2float(hz), lw = v.w - __half2float(hw);
    l0 = __halves2half2(__float2half_rn(lx), __float2half_rn(ly));
    l1 = __halves2half2(__float2half_rn(lz), __float2half_rn(lw));
}

// ---------------------------------------------------------------------------
// HGEMM (fp16x3, fp32-accurate): C = A(M,K) @ B(N,K)^T (+bias, relu).
// 128x128 block, 8 warps (2x4), warp tile 64x32, K staged 32.
// grid = (N/128, M/128, splitK). K, kChunk multiples of 32.
// ---------------------------------------------------------------------------
template <bool RELU, bool BIAS>
__global__ __launch_bounds__(256)
void hgemm(const float* __restrict__ A, const float* __restrict__ B,
           const float* __restrict__ bias, float* __restrict__ C,
           int N, int K, int kChunk, int partStride) {
    // rows padded to 40 halves (20 b32) -> conflict-free fragment loads
    __shared__ __half Ahi[128 * 40], Alo[128 * 40], Bhi[128 * 40], Blo[128 * 40];

    const int tid = threadIdx.x;
    const int lane = tid & 31, wid = tid >> 5;
    const int wm = wid >> 2, wn = wid & 3;          // 2 x 4 warp grid
    const int g = lane >> 2, tig = lane & 3;
    const int m0 = blockIdx.y * 128, n0 = blockIdx.x * 128;
    float* Cp = C + (size_t)blockIdx.z * partStride;
    const float* Ag = A + (size_t)m0 * K + (size_t)blockIdx.z * kChunk;
    const float* Bg = B + (size_t)n0 * K + (size_t)blockIdx.z * kChunk;

    float acc[4][4][4];
#pragma unroll
    for (int mt = 0; mt < 4; mt++)
#pragma unroll
        for (int nt = 0; nt < 4; nt++)
#pragma unroll
            for (int q = 0; q < 4; q++) acc[mt][nt][q] = 0.f;

    const int nStages = kChunk >> 5;
    for (int s = 0; s < nStages; s++) {
        const int kk = s << 5;
        __syncthreads();
#pragma unroll
        for (int it = 0; it < 4; it++) {
            int i = tid + it * 256;                 // 1024 float4 per tensor
            int row = i >> 3, c4 = (i & 7) * 4;
            float4 va = *(const float4*)(Ag + (size_t)row * K + kk + c4);
            float4 vb = *(const float4*)(Bg + (size_t)row * K + kk + c4);
            __half2 h0, h1, l0, l1;
            split4(va, h0, h1, l0, l1);
            int idx = row * 40 + c4;
            *(__half2*)&Ahi[idx] = h0; *(__half2*)&Ahi[idx + 2] = h1;
            *(__half2*)&Alo[idx] = l0; *(__half2*)&Alo[idx + 2] = l1;
            split4(vb, h0, h1, l0, l1);
            *(__half2*)&Bhi[idx] = h0; *(__half2*)&Bhi[idx + 2] = h1;
            *(__half2*)&Blo[idx] = l0; *(__half2*)&Blo[idx + 2] = l1;
        }
        __syncthreads();
#pragma unroll
        for (int ks = 0; ks < 32; ks += 16) {
            uint32_t ah[4][4], bh[4][2], bl[4][2], al[4][4];
#pragma unroll
            for (int mt = 0; mt < 4; mt++) {
                int rb = (wm * 64 + mt * 16) * 40 + ks + tig * 2;
                ah[mt][0] = *(const uint32_t*)&Ahi[rb + g * 40];
                ah[mt][1] = *(const uint32_t*)&Ahi[rb + (g + 8) * 40];
                ah[mt][2] = *(const uint32_t*)&Ahi[rb + g * 40 + 8];
                ah[mt][3] = *(const uint32_t*)&Ahi[rb + (g + 8) * 40 + 8];
            }
#pragma unroll
            for (int nt = 0; nt < 4; nt++) {
                int rb = (wn * 32 + nt * 8 + g) * 40 + ks + tig * 2;
                bh[nt][0] = *(const uint32_t*)&Bhi[rb];
                bh[nt][1] = *(const uint32_t*)&Bhi[rb + 8];
            }
#pragma unroll
            for (int mt = 0; mt < 4; mt++)
#pragma unroll
                for (int nt = 0; nt < 4; nt++)
                    mma16816(acc[mt][nt], ah[mt], bh[nt]);   // hi*hi
#pragma unroll
            for (int nt = 0; nt < 4; nt++) {
                int rb = (wn * 32 + nt * 8 + g) * 40 + ks + tig * 2;
                bl[nt][0] = *(const uint32_t*)&Blo[rb];
                bl[nt][1] = *(const uint32_t*)&Blo[rb + 8];
            }
#pragma unroll
            for (int mt = 0; mt < 4; mt++)
#pragma unroll
                for (int nt = 0; nt < 4; nt++)
                    mma16816(acc[mt][nt], ah[mt], bl[nt]);   // hi*lo
#pragma unroll
            for (int mt = 0; mt < 4; mt++) {
                int rb = (wm * 64 + mt * 16) * 40 + ks + tig * 2;
                al[mt][0] = *(const uint32_t*)&Alo[rb + g * 40];
                al[mt][1] = *(const uint32_t*)&Alo[rb + (g + 8) * 40];
                al[mt][2] = *(const uint32_t*)&Alo[rb + g * 40 + 8];
                al[mt][3] = *(const uint32_t*)&Alo[rb + (g + 8) * 40 + 8];
            }
#pragma unroll
            for (int mt = 0; mt < 4; mt++)
#pragma unroll
                for (int nt = 0; nt < 4; nt++)
                    mma16816(acc[mt][nt], al[mt], bh[nt]);   // lo*hi
        }
    }

    // epilogue: float2 stores, c0c1 at (row, col), c2c3 at (row+8, col)
#pragma unroll
    for (int mt = 0; mt < 4; mt++) {
        int row = m0 + wm * 64 + mt * 16 + g;
#pragma unroll
        for (int nt = 0; nt < 4; nt++) {
            int col = n0 + wn * 32 + nt * 8 + tig * 2;
            float b0 = 0.f, b1 = 0.f;
            if (BIAS) { b0 = bias[col]; b1 = bias[col + 1]; }
            float2 v0 = make_float2(acc[mt][nt][0] + b0, acc[mt][nt][1] + b1);
            float2 v1 = make_float2(acc[mt][nt][2] + b0, acc[mt][nt][3] + b1);
            if (RELU) {
                v0.x = fmaxf(v0.x, 0.f); v0.y = fmaxf(v0.y, 0.f);
                v1.x = fmaxf(v1.x, 0.f); v1.y = fmaxf(v1.y, 0.f);
            }
            *(float2*)(Cp + (size_t)row * N + col) = v0;
            *(float2*)(Cp + (size_t)(row + 8) * N + col) = v1;
        }
    }
}

// ---------------------------------------------------------------------------
// 1) tile + /255
// ---------------------------------------------------------------------------
__global__ void k_tile(const float* __restrict__ t) {
    int img = blockIdx.x;
    int b = img >> 4, tile = img & 15;
    int r4 = tile >> 2, c4 = tile & 3;
    const float* src = t + b * 16384 + (r4 * 32) * 128 + c4 * 32;
    float* dst = g_tiles + img * 1024;
    for (int i = threadIdx.x; i < 1024; i += 256) {
        int r = i >> 5, c = i & 31;
        dst[i] = src[r * 128 + c] * (1.0f / 255.0f);
    }
}

// ---------------------------------------------------------------------------
// 2) conv1 + pool
// ---------------------------------------------------------------------------
__global__ void k_conv1(const float* __restrict__ w, const float* __restrict__ bias) {
    __shared__ float sim[1024];
    __shared__ float sw[288];
    __shared__ float sb[32];
    int img = blockIdx.x;
    int tid = threadIdx.x;
    for (int i = tid; i < 1024; i += 256) sim[i] = g_tiles[img * 1024 + i];
    for (int i = tid; i < 288; i += 256) sw[i] = w[i];
    if (tid < 32) sb[tid] = bias[tid];
    __syncthreads();
    if (tid >= 225) return;
    int oi = tid / 15, oj = tid % 15;
    float p[4][4];
#pragma unroll
    for (int r = 0; r < 4; r++)
#pragma unroll
        for (int c = 0; c < 4; c++)
            p[r][c] = sim[(2 * oi + r) * 32 + (2 * oj + c)];
    float* o = g_p1 + img * 7200 + tid;
#pragma unroll 4
    for (int oc = 0; oc < 32; oc++) {
        float a0 = 0.f, a1 = 0.f, a2 = 0.f, a3 = 0.f;
#pragma unroll
        for (int ky = 0; ky < 3; ky++)
#pragma unroll
            for (int kx = 0; kx < 3; kx++) {
                float wv = sw[oc * 9 + ky * 3 + kx];
                a0 = fmaf(p[ky][kx], wv, a0);
                a1 = fmaf(p[ky][kx + 1], wv, a1);
                a2 = fmaf(p[ky + 1][kx], wv, a2);
                a3 = fmaf(p[ky + 1][kx + 1], wv, a3);
            }
        o[oc * 225] = fmaxf(fmaxf(a0, a1), fmaxf(a2, a3)) + sb[oc];
    }
}

// ---------------------------------------------------------------------------
// 3) conv2 + pool
// ---------------------------------------------------------------------------
__global__ void k_conv2(const float* __restrict__ w, const float* __restrict__ bias) {
    extern __shared__ float sm2[];
    float* sin = sm2;
    float* sw  = sm2 + 7200;
    __shared__ float sb[32];
    int img = blockIdx.x;
    int tid = threadIdx.x;
    for (int i = tid; i < 7200; i += 256) sin[i] = g_p1[img * 7200 + i];
    for (int i = tid; i < 9216; i += 256) sw[i] = w[i];
    if (tid < 32) sb[tid] = bias[tid];
    __syncthreads();
    for (int idx = tid; idx < 1152; idx += 256) {
        int oc = idx / 36, pos = idx % 36;
        int oi = pos / 6, oj = pos % 6;
        int y0 = 2 * oi, x0 = 2 * oj;
        float a0 = 0.f, a1 = 0.f, a2 = 0.f, a3 = 0.f;
        const float* wp = sw + oc * 288;
        for (int ic = 0; ic < 32; ic++) {
            const float* ip = sin + ic * 225 + y0 * 15 + x0;
            float p[4][4];
#pragma unroll
            for (int r = 0; r < 4; r++)
#pragma unroll
                for (int c = 0; c < 4; c++) p[r][c] = ip[r * 15 + c];
#pragma unroll
            for (int ky = 0; ky < 3; ky++)
#pragma unroll
                for (int kx = 0; kx < 3; kx++) {
                    float wv = wp[ic * 9 + ky * 3 + kx];
                    a0 = fmaf(p[ky][kx], wv, a0);
                    a1 = fmaf(p[ky][kx + 1], wv, a1);
                    a2 = fmaf(p[ky + 1][kx], wv, a2);
                    a3 = fmaf(p[ky + 1][kx + 1], wv, a3);
                }
        }
        g_p2[img * 1152 + idx] = fmaxf(fmaxf(a0, a1), fmaxf(a2, a3)) + sb[oc];
    }
}

// ---------------------------------------------------------------------------
// 4) expand: relu((131072,36)@(64,36)^T+b). 64 rows/block, 16 out/thread.
// ---------------------------------------------------------------------------
__global__ void k_expand(const float* __restrict__ w, const float* __restrict__ bias) {
    __shared__ float sw[36 * 64];
    __shared__ float sb[64];
    __shared__ float srow[64 * 37];
    int tid = threadIdx.x;           // 256
    for (int i = tid; i < 2304; i += 256) {
        int e = i / 36, d = i % 36;
        sw[d * 64 + e] = w[i];
    }
    if (tid < 64) sb[tid] = bias[tid];
    int row0 = blockIdx.x * 64;
    for (int i = tid; i < 2304; i += 256) {
        int r = i / 36, d = i % 36;
        srow[r * 37 + d] = g_p2[(size_t)row0 * 36 + i];
    }
    __syncthreads();
    int r = tid >> 2, q = tid & 3;
    float acc[16];
#pragma unroll
    for (int j = 0; j < 16; j++) acc[j] = sb[q * 16 + j];
    for (int d = 0; d < 36; d++) {
        float a = srow[r * 37 + d];
        const float* wp = sw + d * 64 + q * 16;
#pragma unroll
        for (int j = 0; j < 16; j++) acc[j] = fmaf(a, wp[j], acc[j]);
    }
    float* op = g_u + (size_t)(row0 + r) * 64 + q * 16;
#pragma unroll
    for (int j = 0; j < 16; j++) op[j] = fmaxf(acc[j], 0.f);
}

// ---------------------------------------------------------------------------
// 5) grouped MHA + residual + LN(64) -> g_x
// ---------------------------------------------------------------------------
__global__ void k_gattn(const float* __restrict__ wqkv, const float* __restrict__ bqkv,
                        const float* __restrict__ wo, const float* __restrict__ bo,
                        const float* __restrict__ lnw, const float* __restrict__ lnb) {
    extern __shared__ float sm5[];
    float* su   = sm5;
    float* sqkv = sm5 + 2048;
    float* ssc  = sm5 + 8224;
    float* so   = sm5 + 12448;
    float* sy   = sm5 + 2048;

    int g = blockIdx.x >> 8, b = blockIdx.x & 255;
    int tid = threadIdx.x;

    for (int i = tid; i < 2048; i += 192) {
        int l = i >> 6, e = i & 63;
        su[i] = g_u[((g * 32 + l) * 256 + b) * 64 + e];
    }
    __syncthreads();
    {
        const float* W = wqkv + (g * 192 + tid) * 64;
        float acc[32];
        float bq = bqkv[g * 192 + tid];
#pragma unroll
        for (int l = 0; l < 32; l++) acc[l] = bq;
        for (int d = 0; d < 64; d++) {
            float wv = __ldg(W + d);
#pragma unroll
            for (int l = 0; l < 32; l++) acc[l] = fmaf(su[l * 64 + d], wv, acc[l]);
        }
#pragma unroll
        for (int l = 0; l < 32; l++) sqkv[l * 193 + tid] = acc[l];
    }
    __syncthreads();
    if (tid < 128) {
        int h = tid >> 5, i = tid & 31;
        float s[32];
        float mx = -1e30f;
        for (int j = 0; j < 32; j++) {
            float acc = 0.f;
#pragma unroll
            for (int d = 0; d < 16; d++)
                acc = fmaf(sqkv[i * 193 + h * 16 + d], sqkv[j * 193 + 64 + h * 16 + d], acc);
            acc *= 0.25f;
            s[j] = acc;
            mx = fmaxf(mx, acc);
        }
        float sum = 0.f;
        for (int j = 0; j < 32; j++) { s[j] = __expf(s[j] - mx); sum += s[j]; }
        float inv = 1.0f / sum;
        for (int j = 0; j < 32; j++) ssc[(h * 32 + i) * 33 + j] = s[j] * inv;
    }
    __syncthreads();
    if (tid < 128) {
        int h = tid >> 5, i = tid & 31;
        float acc[16];
#pragma unroll
        for (int d = 0; d < 16; d++) acc[d] = 0.f;
        for (int j = 0; j < 32; j++) {
            float a = ssc[(h * 32 + i) * 33 + j];
#pragma unroll
            for (int d = 0; d < 16; d++)
                acc[d] = fmaf(a, sqkv[j * 193 + 128 + h * 16 + d], acc[d]);
        }
#pragma unroll
        for (int d = 0; d < 16; d++) so[i * 65 + h * 16 + d] = acc[d];
    }
    __syncthreads();
    for (int idx = tid; idx < 2048; idx += 192) {
        int l = idx >> 6, oo = idx & 63;
        const float* W = wo + g * 4096 + oo * 64;
        float acc = bo[g * 64 + oo];
#pragma unroll 8
        for (int e = 0; e < 64; e++) acc = fmaf(so[l * 65 + e], __ldg(W + e), acc);
        sy[idx] = acc + su[idx];
    }
    __syncthreads();
    int warp = tid >> 5, lane = tid & 31;
    for (int l = warp; l < 32; l += 6) {
        float v0 = sy[l * 64 + lane], v1 = sy[l * 64 + 32 + lane];
        float s = v0 + v1, s2 = v0 * v0 + v1 * v1;
#pragma unroll
        for (int o = 16; o; o >>= 1) {
            s += __shfl_xor_sync(0xffffffffu, s, o);
            s2 += __shfl_xor_sync(0xffffffffu, s2, o);
        }
        float mu = s * (1.0f / 64.0f);
        float var = s2 * (1.0f / 64.0f) - mu * mu;
        float inv = rsqrtf(var + 1e-5f);
        int base = ((g * 32 + l) * 256 + b) * 64;
        g_x[base + lane]      = (v0 - mu) * inv * lnw[lane] + lnb[lane];
        g_x[base + 32 + lane] = (v1 - mu) * inv * lnw[32 + lane] + lnb[32 + lane];
    }
}

// ---------------------------------------------------------------------------
// encoder attention
// ---------------------------------------------------------------------------
__global__ void k_encattn() {
    __shared__ float sq[16 * 128];
    __shared__ float sk[16 * 129];
    __shared__ float sv[16 * 129];
    __shared__ float ss[16 * 16];
    int b = blockIdx.x >> 4, h = blockIdx.x & 15;
    int tid = threadIdx.x;
    const float scale = 0.08838834764831845f;
    for (int i = tid; i < 2048; i += 128) {
        int l = i >> 7, d = i & 127;
        int base = (l * 256 + b) * 6144 + h * 128 + d;
        sq[l * 128 + d] = g_qkv[base] * scale;
        sk[l * 129 + d] = g_qkv[base + 2048];
        sv[l * 129 + d] = g_qkv[base + 4096];
    }
    __syncthreads();
    for (int idx = tid; idx < 256; idx += 128) {
        int i = idx >> 4, j = idx & 15;
        float acc = 0.f;
#pragma unroll 8
        for (int d = 0; d < 128; d++) acc = fmaf(sq[i * 128 + d], sk[j * 129 + d], acc);
        ss[idx] = acc;
    }
    __syncthreads();
    if (tid < 16) {
        float mx = -1e30f;
        for (int j = 0; j < 16; j++) mx = fmaxf(mx, ss[tid * 16 + j]);
        float sum = 0.f;
        for (int j = 0; j < 16; j++) { float e = __expf(ss[tid * 16 + j] - mx); ss[tid * 16 + j] = e; sum += e; }
        float inv = 1.0f / sum;
        for (int j = 0; j < 16; j++) ss[tid * 16 + j] *= inv;
    }
    __syncthreads();
    for (int idx = tid; idx < 2048; idx += 128) {
        int i = idx >> 7, d = idx & 127;
        float acc = 0.f;
#pragma unroll
        for (int j = 0; j < 16; j++) acc = fmaf(ss[i * 16 + j], sv[j * 129 + d], acc);
        g_att[(i * 256 + b) * 2048 + h * 128 + d] = acc;
    }
}

// ---------------------------------------------------------------------------
// LN over 2048 with residual
// ---------------------------------------------------------------------------
__global__ void k_ln2048(const float* __restrict__ x, const float* __restrict__ r,
                         const float* __restrict__ w, const float* __restrict__ b,
                         float* __restrict__ out) {
    int row = blockIdx.x, tid = threadIdx.x;
    const float* xp = x + (size_t)row * 2048;
    const float* rp = r + (size_t)row * 2048;
    float v[8];
    float s = 0.f, s2 = 0.f;
#pragma unroll
    for (int i = 0; i < 8; i++) {
        float t = xp[tid + i * 256] + rp[tid + i * 256];
        v[i] = t; s += t; s2 += t * t;
    }
    __shared__ float sh[64];
#pragma unroll
    for (int o = 16; o; o >>= 1) {
        s += __shfl_xor_sync(0xffffffffu, s, o);
        s2 += __shfl_xor_sync(0xffffffffu, s2, o);
    }
    int warp = tid >> 5, lane = tid & 31;
    if (lane == 0) { sh[warp] = s; sh[32 + warp] = s2; }
    __syncthreads();
    if (warp == 0) {
        s = (lane < 8) ? sh[lane] : 0.f;
        s2 = (lane < 8) ? sh[32 + lane] : 0.f;
#pragma unroll
        for (int o = 4; o; o >>= 1) {
            s += __shfl_xor_sync(0xffffffffu, s, o);
            s2 += __shfl_xor_sync(0xffffffffu, s2, o);
        }
        if (lane == 0) { sh[0] = s; sh[1] = s2; }
    }
    __syncthreads();
    float mu = sh[0] * (1.0f / 2048.0f);
    float var = sh[1] * (1.0f / 2048.0f) - mu * mu;
    float inv = rsqrtf(var + 1e-5f);
#pragma unroll
    for (int i = 0; i < 8; i++) {
        int c = tid + i * 256;
        out[(size_t)row * 2048 + c] = (v[i] - mu) * inv * w[c] + b[c];
    }
}

// ---------------------------------------------------------------------------
// tails
// ---------------------------------------------------------------------------
__global__ void k_f1red(const float* __restrict__ bias) {
    int idx = blockIdx.x * 256 + threadIdx.x;
    float s = bias[idx & 511];
#pragma unroll
    for (int z = 0; z < 32; z++) s += g_f1p[z * 131072 + idx];
    g_f1o[idx] = fmaxf(s, 0.f);
}

__global__ void k_f2(const float* __restrict__ w, const float* __restrict__ bias) {
    __shared__ float srow[512];
    int b = blockIdx.x, tid = threadIdx.x;
    for (int i = tid; i < 512; i += 128) srow[i] = g_f1o[b * 512 + i];
    __syncthreads();
    float acc = bias[tid];
    const float* wp = w + tid * 512;
#pragma unroll 8
    for (int d = 0; d < 512; d++) acc = fmaf(srow[d], __ldg(wp + d), acc);
    g_f2o[b * 128 + tid] = fmaxf(acc, 0.f);
}

__global__ void k_f3(const float* __restrict__ w, const float* __restrict__ bias,
                     float* __restrict__ out) {
    __shared__ float srow[128];
    int b = blockIdx.x, tid = threadIdx.x;
    for (int i = tid; i < 128; i += 32) srow[i] = g_f2o[b * 128 + i];
    __syncthreads();
    if (tid < 25) {
        float acc = bias[tid];
        const float* wp = w + tid * 128;
#pragma unroll
        for (int d = 0; d < 128; d++) acc = fmaf(srow[d], wp[d], acc);
        out[b * 25 + tid] = acc;
    }
}

// ---------------------------------------------------------------------------
// launch
// ---------------------------------------------------------------------------
extern "C" void kernel_launch(void* const* d_in, const int* in_sizes, int n_in,
                              void* d_out, int out_size) {
    const float* t        = (const float*)d_in[0];
    const float* conv1_w  = (const float*)d_in[1];
    const float* conv1_b  = (const float*)d_in[2];
    const float* conv2_w  = (const float*)d_in[3];
    const float* conv2_b  = (const float*)d_in[4];
    const float* expand_w = (const float*)d_in[5];
    const float* expand_b = (const float*)d_in[6];
    const float* mha_wqkv = (const float*)d_in[7];
    const float* mha_bqkv = (const float*)d_in[8];
    const float* mha_wo   = (const float*)d_in[9];
    const float* mha_bo   = (const float*)d_in[10];
    const float* ln1_w    = (const float*)d_in[11];
    const float* ln1_b    = (const float*)d_in[12];
    const float* enc_wqkv = (const float*)d_in[13];
    const float* enc_bqkv = (const float*)d_in[14];
    const float* enc_wo   = (const float*)d_in[15];
    const float* enc_bo   = (const float*)d_in[16];
    const float* enc_ln1w = (const float*)d_in[17];
    const float* enc_ln1b = (const float*)d_in[18];
    const float* enc_w1   = (const float*)d_in[19];
    const float* enc_b1   = (const float*)d_in[20];
    const float* enc_w2   = (const float*)d_in[21];
    const float* enc_b2   = (const float*)d_in[22];
    const float* enc_ln2w = (const float*)d_in[23];
    const float* enc_ln2b = (const float*)d_in[24];
    const float* f1_w     = (const float*)d_in[25];
    const float* f1_b     = (const float*)d_in[26];
    const float* f2_w     = (const float*)d_in[27];
    const float* f2_b     = (const float*)d_in[28];
    const float* f3_w     = (const float*)d_in[29];
    const float* f3_b     = (const float*)d_in[30];
    float* out = (float*)d_out;

    cudaFuncSetAttribute(k_conv2, cudaFuncAttributeMaxDynamicSharedMemorySize, 65664);
    cudaFuncSetAttribute(k_gattn, cudaFuncAttributeMaxDynamicSharedMemorySize, 58112);

    float *p_x, *p_qkv, *p_att, *p_tmp, *p_x1, *p_h2, *p_x2, *p_f1p;
    cudaGetSymbolAddress((void**)&p_x,   g_x);
    cudaGetSymbolAddress((void**)&p_qkv, g_qkv);
    cudaGetSymbolAddress((void**)&p_att, g_att);
    cudaGetSymbolAddress((void**)&p_tmp, g_tmp);
    cudaGetSymbolAddress((void**)&p_x1,  g_x1);
    cudaGetSymbolAddress((void**)&p_h2,  g_h2);
    cudaGetSymbolAddress((void**)&p_x2,  g_x2);
    cudaGetSymbolAddress((void**)&p_f1p, g_f1p);

    k_tile<<<4096, 256>>>(t);
    k_conv1<<<4096, 256>>>(conv1_w, conv1_b);
    k_conv2<<<4096, 256, 65664>>>(conv2_w, conv2_b);
    k_expand<<<2048, 256>>>(expand_w, expand_b);
    k_gattn<<<4096, 192, 58112>>>(mha_wqkv, mha_bqkv, mha_wo, mha_bo, ln1_w, ln1_b);

    // qkv: (4096,2048) @ (6144,2048)^T
    hgemm<false, true><<<dim3(48, 32, 1), 256>>>(p_x, enc_wqkv, enc_bqkv, p_qkv,
                                                 6144, 2048, 2048, 0);
    k_encattn<<<4096, 128>>>();
    hgemm<false, true><<<dim3(16, 32, 1), 256>>>(p_att, enc_wo, enc_bo, p_tmp,
                                                 2048, 2048, 2048, 0);
    k_ln2048<<<4096, 256>>>(p_x, p_tmp, enc_ln1w, enc_ln1b, p_x1);
    hgemm<true, true><<<dim3(16, 32, 1), 256>>>(p_x1, enc_w1, enc_b1, p_h2,
                                                2048, 2048, 2048, 0);
    hgemm<false, true><<<dim3(16, 32, 1), 256>>>(p_h2, enc_w2, enc_b2, p_tmp,
                                                 2048, 2048, 2048, 0);
    k_ln2048<<<4096, 256>>>(p_x1, p_tmp, enc_ln2w, enc_ln2b, p_x2);

    // f1: (256,32768) @ (512,32768)^T, split-K 32
    hgemm<false, false><<<dim3(4, 2, 32), 256>>>(p_x2, f1_w, nullptr, p_f1p,
                                                 512, 32768, 1024, 256 * 512);
    k_f1red<<<512, 256>>>(f1_b);
    k_f2<<<256, 128>>>(f2_w, f2_b);
    k_f3<<<256, 32>>>(f3_w, f3_b, out);
}

// round 6
// speedup vs baseline: 1.8184x; 1.4023x over previous
#include <cuda_runtime.h>
#include <cuda_fp16.h>
#include <math.h>
#include <stdint.h>

// ---------------------------------------------------------------------------
// Scratch
// ---------------------------------------------------------------------------
__device__ float g_tiles[4096 * 1024];
__device__ float g_p1[4096 * 32 * 225];
__device__ float g_p2[4096 * 32 * 36];
__device__ float g_u[4096 * 2048];
__device__ float g_x[4096 * 2048];
__device__ float g_qkv[4096 * 6144];
__device__ float g_att[4096 * 2048];
__device__ float g_tmp[4096 * 2048];
__device__ float g_x1[4096 * 2048];
__device__ float g_h2[4096 * 2048];
__device__ float g_x2[4096 * 2048];
__device__ float g_f1p[32 * 256 * 512];
__device__ float g_f1o[256 * 512];
__device__ float g_f2o[256 * 128];

// ---------------------------------------------------------------------------
// mma.sync m16n8k16 fp16 -> fp32
// ---------------------------------------------------------------------------
__device__ __forceinline__ void mma16816(float* c, const uint32_t* a, const uint32_t* b) {
    asm volatile(
        "mma.sync.aligned.m16n8k16.row.col.f32.f16.f16.f32 "
        "{%0,%1,%2,%3}, {%4,%5,%6,%7}, {%8,%9}, {%0,%1,%2,%3};"
        : "+f"(c[0]), "+f"(c[1]), "+f"(c[2]), "+f"(c[3])
        : "r"(a[0]), "r"(a[1]), "r"(a[2]), "r"(a[3]), "r"(b[0]), "r"(b[1]));
}

// fp32x4 -> fp16 hi (rounded) + fp16 lo (rounded residual)
__device__ __forceinline__ void split4(float4 v, __half2& h0, __half2& h1,
                                       __half2& l0, __half2& l1) {
    __half hx = __float2half_rn(v.x), hy = __float2half_rn(v.y);
    __half hz = __float2half_rn(v.z), hw = __float2half_rn(v.w);
    h0 = __halves2half2(hx, hy);
    h1 = __halves2half2(hz, hw);
    float lx = v.x - __half2float(hx), ly = v.y - __half2float(hy);
    float lz = v.z - __half2float(hz), lw = v.w - __half2float(hw);
    l0 = __halves2half2(__float2half_rn(lx), __float2half_rn(ly));
    l1 = __halves2half2(__float2half_rn(lz), __float2half_rn(lw));
}

// ---------------------------------------------------------------------------
// HGEMM (fp16x3): C = A(M,K) @ B(N,K)^T (+bias, relu).
// 128x128 block, 8 warps (2x4), warp tile 64x32, K staged 32, DOUBLE-BUFFERED.
// grid = (N/128, M/128, splitK). K, kChunk multiples of 32.
// Dynamic smem: 2 stages x (4 tensors x 128 x 40 halves) = 81920 B.
// ---------------------------------------------------------------------------
#define HG_SMEM 81920
#define HG_STAGE 20480   // halves per stage

template <bool RELU, bool BIAS>
__global__ __launch_bounds__(256)
void hgemm(const float* __restrict__ A, const float* __restrict__ B,
           const float* __restrict__ bias, float* __restrict__ C,
           int N, int K, int kChunk, int partStride) {
    extern __shared__ __half sh[];

    const int tid = threadIdx.x;
    const int lane = tid & 31, wid = tid >> 5;
    const int wm = wid >> 2, wn = wid & 3;          // 2 x 4 warp grid
    const int g = lane >> 2, tig = lane & 3;
    const int m0 = blockIdx.y * 128, n0 = blockIdx.x * 128;
    float* Cp = C + (size_t)blockIdx.z * partStride;
    const float* Ag = A + (size_t)m0 * K + (size_t)blockIdx.z * kChunk;
    const float* Bg = B + (size_t)n0 * K + (size_t)blockIdx.z * kChunk;

    const int r0 = tid >> 3;            // 0..31 (+32 per iter)
    const int c4 = (tid & 7) * 4;       // 0..28

    float acc[4][4][4];
#pragma unroll
    for (int mt = 0; mt < 4; mt++)
#pragma unroll
        for (int nt = 0; nt < 4; nt++)
#pragma unroll
            for (int q = 0; q < 4; q++) acc[mt][nt][q] = 0.f;

    float4 va[4], vb[4];
    // prefetch stage 0
#pragma unroll
    for (int it = 0; it < 4; it++) {
        int row = r0 + it * 32;
        va[it] = *(const float4*)(Ag + (size_t)row * K + c4);
        vb[it] = *(const float4*)(Bg + (size_t)row * K + c4);
    }

    const int nStages = kChunk >> 5;
    for (int s = 0; s < nStages; s++) {
        __half* Ahi = sh + (s & 1) * HG_STAGE;
        __half* Alo = Ahi + 5120;
        __half* Bhi = Ahi + 10240;
        __half* Blo = Ahi + 15360;

        // convert + store current stage
#pragma unroll
        for (int it = 0; it < 4; it++) {
            int idx = (r0 + it * 32) * 40 + c4;
            __half2 h0, h1, l0, l1;
            split4(va[it], h0, h1, l0, l1);
            *(__half2*)&Ahi[idx] = h0; *(__half2*)&Ahi[idx + 2] = h1;
            *(__half2*)&Alo[idx] = l0; *(__half2*)&Alo[idx + 2] = l1;
            split4(vb[it], h0, h1, l0, l1);
            *(__half2*)&Bhi[idx] = h0; *(__half2*)&Bhi[idx + 2] = h1;
            *(__half2*)&Blo[idx] = l0; *(__half2*)&Blo[idx + 2] = l1;
        }
        __syncthreads();

        // prefetch next stage into registers (overlaps with MMA below)
        if (s + 1 < nStages) {
            int kk = (s + 1) << 5;
#pragma unroll
            for (int it = 0; it < 4; it++) {
                int row = r0 + it * 32;
                va[it] = *(const float4*)(Ag + (size_t)row * K + kk + c4);
                vb[it] = *(const float4*)(Bg + (size_t)row * K + kk + c4);
            }
        }

#pragma unroll
        for (int ks = 0; ks < 32; ks += 16) {
            uint32_t ah[4][4], bh[4][2], bl[4][2], al[4][4];
#pragma unroll
            for (int mt = 0; mt < 4; mt++) {
                int rb = (wm * 64 + mt * 16) * 40 + ks + tig * 2;
                ah[mt][0] = *(const uint32_t*)&Ahi[rb + g * 40];
                ah[mt][1] = *(const uint32_t*)&Ahi[rb + (g + 8) * 40];
                ah[mt][2] = *(const uint32_t*)&Ahi[rb + g * 40 + 8];
                ah[mt][3] = *(const uint32_t*)&Ahi[rb + (g + 8) * 40 + 8];
            }
#pragma unroll
            for (int nt = 0; nt < 4; nt++) {
                int rb = (wn * 32 + nt * 8 + g) * 40 + ks + tig * 2;
                bh[nt][0] = *(const uint32_t*)&Bhi[rb];
                bh[nt][1] = *(const uint32_t*)&Bhi[rb + 8];
            }
#pragma unroll
            for (int mt = 0; mt < 4; mt++)
#pragma unroll
                for (int nt = 0; nt < 4; nt++)
                    mma16816(acc[mt][nt], ah[mt], bh[nt]);   // hi*hi
#pragma unroll
            for (int nt = 0; nt < 4; nt++) {
                int rb = (wn * 32 + nt * 8 + g) * 40 + ks + tig * 2;
                bl[nt][0] = *(const uint32_t*)&Blo[rb];
                bl[nt][1] = *(const uint32_t*)&Blo[rb + 8];
            }
#pragma unroll
            for (int mt = 0; mt < 4; mt++)
#pragma unroll
                for (int nt = 0; nt < 4; nt++)
                    mma16816(acc[mt][nt], ah[mt], bl[nt]);   // hi*lo
#pragma unroll
            for (int mt = 0; mt < 4; mt++) {
                int rb = (wm * 64 + mt * 16) * 40 + ks + tig * 2;
                al[mt][0] = *(const uint32_t*)&Alo[rb + g * 40];
                al[mt][1] = *(const uint32_t*)&Alo[rb + (g + 8) * 40];
                al[mt][2] = *(const uint32_t*)&Alo[rb + g * 40 + 8];
                al[mt][3] = *(const uint32_t*)&Alo[rb + (g + 8) * 40 + 8];
            }
#pragma unroll
            for (int mt = 0; mt < 4; mt++)
#pragma unroll
                for (int nt = 0; nt < 4; nt++)
                    mma16816(acc[mt][nt], al[mt], bh[nt]);   // lo*hi
        }
    }

    // epilogue
#pragma unroll
    for (int mt = 0; mt < 4; mt++) {
        int row = m0 + wm * 64 + mt * 16 + g;
#pragma unroll
        for (int nt = 0; nt < 4; nt++) {
            int col = n0 + wn * 32 + nt * 8 + tig * 2;
            float b0 = 0.f, b1 = 0.f;
            if (BIAS) { b0 = bias[col]; b1 = bias[col + 1]; }
            float2 v0 = make_float2(acc[mt][nt][0] + b0, acc[mt][nt][1] + b1);
            float2 v1 = make_float2(acc[mt][nt][2] + b0, acc[mt][nt][3] + b1);
            if (RELU) {
                v0.x = fmaxf(v0.x, 0.f); v0.y = fmaxf(v0.y, 0.f);
                v1.x = fmaxf(v1.x, 0.f); v1.y = fmaxf(v1.y, 0.f);
            }
            *(float2*)(Cp + (size_t)row * N + col) = v0;
            *(float2*)(Cp + (size_t)(row + 8) * N + col) = v1;
        }
    }
}

// ---------------------------------------------------------------------------
// 1) tile + /255
// ---------------------------------------------------------------------------
__global__ void k_tile(const float* __restrict__ t) {
    int img = blockIdx.x;
    int b = img >> 4, tile = img & 15;
    int r4 = tile >> 2, c4 = tile & 3;
    const float* src = t + b * 16384 + (r4 * 32) * 128 + c4 * 32;
    float* dst = g_tiles + img * 1024;
    for (int i = threadIdx.x; i < 1024; i += 256) {
        int r = i >> 5, c = i & 31;
        dst[i] = src[r * 128 + c] * (1.0f / 255.0f);
    }
}

// ---------------------------------------------------------------------------
// 2) conv1 + pool
// ---------------------------------------------------------------------------
__global__ void k_conv1(const float* __restrict__ w, const float* __restrict__ bias) {
    __shared__ float sim[1024];
    __shared__ float sw[288];
    __shared__ float sb[32];
    int img = blockIdx.x;
    int tid = threadIdx.x;
    for (int i = tid; i < 1024; i += 256) sim[i] = g_tiles[img * 1024 + i];
    for (int i = tid; i < 288; i += 256) sw[i] = w[i];
    if (tid < 32) sb[tid] = bias[tid];
    __syncthreads();
    if (tid >= 225) return;
    int oi = tid / 15, oj = tid % 15;
    float p[4][4];
#pragma unroll
    for (int r = 0; r < 4; r++)
#pragma unroll
        for (int c = 0; c < 4; c++)
            p[r][c] = sim[(2 * oi + r) * 32 + (2 * oj + c)];
    float* o = g_p1 + img * 7200 + tid;
#pragma unroll 4
    for (int oc = 0; oc < 32; oc++) {
        float a0 = 0.f, a1 = 0.f, a2 = 0.f, a3 = 0.f;
#pragma unroll
        for (int ky = 0; ky < 3; ky++)
#pragma unroll
            for (int kx = 0; kx < 3; kx++) {
                float wv = sw[oc * 9 + ky * 3 + kx];
                a0 = fmaf(p[ky][kx], wv, a0);
                a1 = fmaf(p[ky][kx + 1], wv, a1);
                a2 = fmaf(p[ky + 1][kx], wv, a2);
                a3 = fmaf(p[ky + 1][kx + 1], wv, a3);
            }
        o[oc * 225] = fmaxf(fmaxf(a0, a1), fmaxf(a2, a3)) + sb[oc];
    }
}

// ---------------------------------------------------------------------------
// 3) conv2 + pool. 288 threads: thread = (4-oc group, position).
//    smem weights transposed to [ic][k][oc] so 4 oc = one LDS.128.
// ---------------------------------------------------------------------------
__global__ void k_conv2(const float* __restrict__ w, const float* __restrict__ bias) {
    extern __shared__ float sm2[];
    float* sin = sm2;            // 7200
    float* sw  = sm2 + 7200;     // 9216 : [ic][k][oc] = ic*288 + k*32 + oc
    __shared__ float sb[32];
    int img = blockIdx.x;
    int tid = threadIdx.x;       // 288
    for (int i = tid; i < 7200; i += 288) sin[i] = g_p1[img * 7200 + i];
    for (int i = tid; i < 9216; i += 288) {
        int oc = i / 288, r = i % 288, ic = r / 9, k = r % 9;
        sw[ic * 288 + k * 32 + oc] = w[i];
    }
    if (tid < 32) sb[tid] = bias[tid];
    __syncthreads();

    int grp = tid / 36, pos = tid % 36;   // grp 0..7
    int oi = pos / 6, oj = pos % 6;
    int y0 = 2 * oi, x0 = 2 * oj;
    int oc0 = grp * 4;
    float acc[4][4];                      // [o][pool-quadrant]
#pragma unroll
    for (int o = 0; o < 4; o++)
#pragma unroll
        for (int q = 0; q < 4; q++) acc[o][q] = 0.f;

    for (int ic = 0; ic < 32; ic++) {
        const float* ip = sin + ic * 225 + y0 * 15 + x0;
        float p[4][4];
#pragma unroll
        for (int r = 0; r < 4; r++)
#pragma unroll
            for (int c = 0; c < 4; c++) p[r][c] = ip[r * 15 + c];
        const float* wbase = sw + ic * 288 + oc0;
#pragma unroll
        for (int k = 0; k < 9; k++) {
            float4 wv = *(const float4*)(wbase + k * 32);
            int ky = k / 3, kx = k % 3;
            const float* wp = &wv.x;
#pragma unroll
            for (int o = 0; o < 4; o++) {
                float wvo = wp[o];
                acc[o][0] = fmaf(p[ky][kx], wvo, acc[o][0]);
                acc[o][1] = fmaf(p[ky][kx + 1], wvo, acc[o][1]);
                acc[o][2] = fmaf(p[ky + 1][kx], wvo, acc[o][2]);
                acc[o][3] = fmaf(p[ky + 1][kx + 1], wvo, acc[o][3]);
            }
        }
    }
#pragma unroll
    for (int o = 0; o < 4; o++) {
        float m = fmaxf(fmaxf(acc[o][0], acc[o][1]), fmaxf(acc[o][2], acc[o][3]));
        g_p2[img * 1152 + (oc0 + o) * 36 + pos] = m + sb[oc0 + o];
    }
}

// ---------------------------------------------------------------------------
// 4) expand: relu((131072,36)@(64,36)^T+b). 64 rows/block, 16 out/thread,
//    float4 weight loads + float4 output stores.
// ---------------------------------------------------------------------------
__global__ void k_expand(const float* __restrict__ w, const float* __restrict__ bias) {
    __shared__ float sw[36 * 64];
    __shared__ float sb[64];
    __shared__ float srow[64 * 37];
    int tid = threadIdx.x;           // 256
    for (int i = tid; i < 2304; i += 256) {
        int e = i / 36, d = i % 36;
        sw[d * 64 + e] = w[i];
    }
    if (tid < 64) sb[tid] = bias[tid];
    int row0 = blockIdx.x * 64;
    for (int i = tid; i < 2304; i += 256) {
        int r = i / 36, d = i % 36;
        srow[r * 37 + d] = g_p2[(size_t)row0 * 36 + i];
    }
    __syncthreads();
    int r = tid >> 2, q = tid & 3;
    float acc[16];
#pragma unroll
    for (int j = 0; j < 16; j++) acc[j] = sb[q * 16 + j];
    for (int d = 0; d < 36; d++) {
        float a = srow[r * 37 + d];
        const float4* wp4 = (const float4*)&sw[d * 64 + q * 16];
#pragma unroll
        for (int j4 = 0; j4 < 4; j4++) {
            float4 wv = wp4[j4];
            acc[j4 * 4 + 0] = fmaf(a, wv.x, acc[j4 * 4 + 0]);
            acc[j4 * 4 + 1] = fmaf(a, wv.y, acc[j4 * 4 + 1]);
            acc[j4 * 4 + 2] = fmaf(a, wv.z, acc[j4 * 4 + 2]);
            acc[j4 * 4 + 3] = fmaf(a, wv.w, acc[j4 * 4 + 3]);
        }
    }
    float* op = g_u + (size_t)(row0 + r) * 64 + q * 16;
#pragma unroll
    for (int j4 = 0; j4 < 4; j4++) {
        float4 o;
        o.x = fmaxf(acc[j4 * 4 + 0], 0.f);
        o.y = fmaxf(acc[j4 * 4 + 1], 0.f);
        o.z = fmaxf(acc[j4 * 4 + 2], 0.f);
        o.w = fmaxf(acc[j4 * 4 + 3], 0.f);
        *(float4*)(op + j4 * 4) = o;
    }
}

// ---------------------------------------------------------------------------
// 5) grouped MHA + residual + LN(64) -> g_x
// ---------------------------------------------------------------------------
__global__ void k_gattn(const float* __restrict__ wqkv, const float* __restrict__ bqkv,
                        const float* __restrict__ wo, const float* __restrict__ bo,
                        const float* __restrict__ lnw, const float* __restrict__ lnb) {
    extern __shared__ float sm5[];
    float* su   = sm5;
    float* sqkv = sm5 + 2048;
    float* ssc  = sm5 + 8224;
    float* so   = sm5 + 12448;
    float* sy   = sm5 + 2048;

    int g = blockIdx.x >> 8, b = blockIdx.x & 255;
    int tid = threadIdx.x;

    for (int i = tid; i < 2048; i += 192) {
        int l = i >> 6, e = i & 63;
        su[i] = g_u[((g * 32 + l) * 256 + b) * 64 + e];
    }
    __syncthreads();
    {
        const float* W = wqkv + (g * 192 + tid) * 64;
        float acc[32];
        float bq = bqkv[g * 192 + tid];
#pragma unroll
        for (int l = 0; l < 32; l++) acc[l] = bq;
        for (int d = 0; d < 64; d++) {
            float wv = __ldg(W + d);
#pragma unroll
            for (int l = 0; l < 32; l++) acc[l] = fmaf(su[l * 64 + d], wv, acc[l]);
        }
#pragma unroll
        for (int l = 0; l < 32; l++) sqkv[l * 193 + tid] = acc[l];
    }
    __syncthreads();
    if (tid < 128) {
        int h = tid >> 5, i = tid & 31;
        float s[32];
        float mx = -1e30f;
        for (int j = 0; j < 32; j++) {
            float acc = 0.f;
#pragma unroll
            for (int d = 0; d < 16; d++)
                acc = fmaf(sqkv[i * 193 + h * 16 + d], sqkv[j * 193 + 64 + h * 16 + d], acc);
            acc *= 0.25f;
            s[j] = acc;
            mx = fmaxf(mx, acc);
        }
        float sum = 0.f;
        for (int j = 0; j < 32; j++) { s[j] = __expf(s[j] - mx); sum += s[j]; }
        float inv = 1.0f / sum;
        for (int j = 0; j < 32; j++) ssc[(h * 32 + i) * 33 + j] = s[j] * inv;
    }
    __syncthreads();
    if (tid < 128) {
        int h = tid >> 5, i = tid & 31;
        float acc[16];
#pragma unroll
        for (int d = 0; d < 16; d++) acc[d] = 0.f;
        for (int j = 0; j < 32; j++) {
            float a = ssc[(h * 32 + i) * 33 + j];
#pragma unroll
            for (int d = 0; d < 16; d++)
                acc[d] = fmaf(a, sqkv[j * 193 + 128 + h * 16 + d], acc[d]);
        }
#pragma unroll
        for (int d = 0; d < 16; d++) so[i * 65 + h * 16 + d] = acc[d];
    }
    __syncthreads();
    for (int idx = tid; idx < 2048; idx += 192) {
        int l = idx >> 6, oo = idx & 63;
        const float* W = wo + g * 4096 + oo * 64;
        float acc = bo[g * 64 + oo];
#pragma unroll 8
        for (int e = 0; e < 64; e++) acc = fmaf(so[l * 65 + e], __ldg(W + e), acc);
        sy[idx] = acc + su[idx];
    }
    __syncthreads();
    int warp = tid >> 5, lane = tid & 31;
    for (int l = warp; l < 32; l += 6) {
        float v0 = sy[l * 64 + lane], v1 = sy[l * 64 + 32 + lane];
        float s = v0 + v1, s2 = v0 * v0 + v1 * v1;
#pragma unroll
        for (int o = 16; o; o >>= 1) {
            s += __shfl_xor_sync(0xffffffffu, s, o);
            s2 += __shfl_xor_sync(0xffffffffu, s2, o);
        }
        float mu = s * (1.0f / 64.0f);
        float var = s2 * (1.0f / 64.0f) - mu * mu;
        float inv = rsqrtf(var + 1e-5f);
        int base = ((g * 32 + l) * 256 + b) * 64;
        g_x[base + lane]      = (v0 - mu) * inv * lnw[lane] + lnb[lane];
        g_x[base + 32 + lane] = (v1 - mu) * inv * lnw[32 + lane] + lnb[32 + lane];
    }
}

// ---------------------------------------------------------------------------
// encoder attention
// ---------------------------------------------------------------------------
__global__ void k_encattn() {
    __shared__ float sq[16 * 128];
    __shared__ float sk[16 * 129];
    __shared__ float sv[16 * 129];
    __shared__ float ss[16 * 16];
    int b = blockIdx.x >> 4, h = blockIdx.x & 15;
    int tid = threadIdx.x;
    const float scale = 0.08838834764831845f;
    for (int i = tid; i < 2048; i += 128) {
        int l = i >> 7, d = i & 127;
        int base = (l * 256 + b) * 6144 + h * 128 + d;
        sq[l * 128 + d] = g_qkv[base] * scale;
        sk[l * 129 + d] = g_qkv[base + 2048];
        sv[l * 129 + d] = g_qkv[base + 4096];
    }
    __syncthreads();
    for (int idx = tid; idx < 256; idx += 128) {
        int i = idx >> 4, j = idx & 15;
        float acc = 0.f;
#pragma unroll 8
        for (int d = 0; d < 128; d++) acc = fmaf(sq[i * 128 + d], sk[j * 129 + d], acc);
        ss[idx] = acc;
    }
    __syncthreads();
    if (tid < 16) {
        float mx = -1e30f;
        for (int j = 0; j < 16; j++) mx = fmaxf(mx, ss[tid * 16 + j]);
        float sum = 0.f;
        for (int j = 0; j < 16; j++) { float e = __expf(ss[tid * 16 + j] - mx); ss[tid * 16 + j] = e; sum += e; }
        float inv = 1.0f / sum;
        for (int j = 0; j < 16; j++) ss[tid * 16 + j] *= inv;
    }
    __syncthreads();
    for (int idx = tid; idx < 2048; idx += 128) {
        int i = idx >> 7, d = idx & 127;
        float acc = 0.f;
#pragma unroll
        for (int j = 0; j < 16; j++) acc = fmaf(ss[i * 16 + j], sv[j * 129 + d], acc);
        g_att[(i * 256 + b) * 2048 + h * 128 + d] = acc;
    }
}

// ---------------------------------------------------------------------------
// LN over 2048 with residual
// ---------------------------------------------------------------------------
__global__ void k_ln2048(const float* __restrict__ x, const float* __restrict__ r,
                         const float* __restrict__ w, const float* __restrict__ b,
                         float* __restrict__ out) {
    int row = blockIdx.x, tid = threadIdx.x;
    const float* xp = x + (size_t)row * 2048;
    const float* rp = r + (size_t)row * 2048;
    float v[8];
    float s = 0.f, s2 = 0.f;
#pragma unroll
    for (int i = 0; i < 8; i++) {
        float t = xp[tid + i * 256] + rp[tid + i * 256];
        v[i] = t; s += t; s2 += t * t;
    }
    __shared__ float sh[64];
#pragma unroll
    for (int o = 16; o; o >>= 1) {
        s += __shfl_xor_sync(0xffffffffu, s, o);
        s2 += __shfl_xor_sync(0xffffffffu, s2, o);
    }
    int warp = tid >> 5, lane = tid & 31;
    if (lane == 0) { sh[warp] = s; sh[32 + warp] = s2; }
    __syncthreads();
    if (warp == 0) {
        s = (lane < 8) ? sh[lane] : 0.f;
        s2 = (lane < 8) ? sh[32 + lane] : 0.f;
#pragma unroll
        for (int o = 4; o; o >>= 1) {
            s += __shfl_xor_sync(0xffffffffu, s, o);
            s2 += __shfl_xor_sync(0xffffffffu, s2, o);
        }
        if (lane == 0) { sh[0] = s; sh[1] = s2; }
    }
    __syncthreads();
    float mu = sh[0] * (1.0f / 2048.0f);
    float var = sh[1] * (1.0f / 2048.0f) - mu * mu;
    float inv = rsqrtf(var + 1e-5f);
#pragma unroll
    for (int i = 0; i < 8; i++) {
        int c = tid + i * 256;
        out[(size_t)row * 2048 + c] = (v[i] - mu) * inv * w[c] + b[c];
    }
}

// ---------------------------------------------------------------------------
// tails
// ---------------------------------------------------------------------------
__global__ void k_f1red(const float* __restrict__ bias) {
    int idx = blockIdx.x * 256 + threadIdx.x;
    float s = bias[idx & 511];
#pragma unroll
    for (int z = 0; z < 32; z++) s += g_f1p[z * 131072 + idx];
    g_f1o[idx] = fmaxf(s, 0.f);
}

__global__ void k_f2(const float* __restrict__ w, const float* __restrict__ bias) {
    __shared__ float srow[512];
    int b = blockIdx.x, tid = threadIdx.x;
    for (int i = tid; i < 512; i += 128) srow[i] = g_f1o[b * 512 + i];
    __syncthreads();
    float acc = bias[tid];
    const float* wp = w + tid * 512;
#pragma unroll 8
    for (int d = 0; d < 512; d++) acc = fmaf(srow[d], __ldg(wp + d), acc);
    g_f2o[b * 128 + tid] = fmaxf(acc, 0.f);
}

__global__ void k_f3(const float* __restrict__ w, const float* __restrict__ bias,
                     float* __restrict__ out) {
    __shared__ float srow[128];
    int b = blockIdx.x, tid = threadIdx.x;
    for (int i = tid; i < 128; i += 32) srow[i] = g_f2o[b * 128 + i];
    __syncthreads();
    if (tid < 25) {
        float acc = bias[tid];
        const float* wp = w + tid * 128;
#pragma unroll
        for (int d = 0; d < 128; d++) acc = fmaf(srow[d], wp[d], acc);
        out[b * 25 + tid] = acc;
    }
}

// ---------------------------------------------------------------------------
// launch
// ---------------------------------------------------------------------------
extern "C" void kernel_launch(void* const* d_in, const int* in_sizes, int n_in,
                              void* d_out, int out_size) {
    const float* t        = (const float*)d_in[0];
    const float* conv1_w  = (const float*)d_in[1];
    const float* conv1_b  = (const float*)d_in[2];
    const float* conv2_w  = (const float*)d_in[3];
    const float* conv2_b  = (const float*)d_in[4];
    const float* expand_w = (const float*)d_in[5];
    const float* expand_b = (const float*)d_in[6];
    const float* mha_wqkv = (const float*)d_in[7];
    const float* mha_bqkv = (const float*)d_in[8];
    const float* mha_wo   = (const float*)d_in[9];
    const float* mha_bo   = (const float*)d_in[10];
    const float* ln1_w    = (const float*)d_in[11];
    const float* ln1_b    = (const float*)d_in[12];
    const float* enc_wqkv = (const float*)d_in[13];
    const float* enc_bqkv = (const float*)d_in[14];
    const float* enc_wo   = (const float*)d_in[15];
    const float* enc_bo   = (const float*)d_in[16];
    const float* enc_ln1w = (const float*)d_in[17];
    const float* enc_ln1b = (const float*)d_in[18];
    const float* enc_w1   = (const float*)d_in[19];
    const float* enc_b1   = (const float*)d_in[20];
    const float* enc_w2   = (const float*)d_in[21];
    const float* enc_b2   = (const float*)d_in[22];
    const float* enc_ln2w = (const float*)d_in[23];
    const float* enc_ln2b = (const float*)d_in[24];
    const float* f1_w     = (const float*)d_in[25];
    const float* f1_b     = (const float*)d_in[26];
    const float* f2_w     = (const float*)d_in[27];
    const float* f2_b     = (const float*)d_in[28];
    const float* f3_w     = (const float*)d_in[29];
    const float* f3_b     = (const float*)d_in[30];
    float* out = (float*)d_out;

    cudaFuncSetAttribute(k_conv2, cudaFuncAttributeMaxDynamicSharedMemorySize, 65664);
    cudaFuncSetAttribute(k_gattn, cudaFuncAttributeMaxDynamicSharedMemorySize, 58112);
    cudaFuncSetAttribute(hgemm<false, true>,  cudaFuncAttributeMaxDynamicSharedMemorySize, HG_SMEM);
    cudaFuncSetAttribute(hgemm<true, true>,   cudaFuncAttributeMaxDynamicSharedMemorySize, HG_SMEM);
    cudaFuncSetAttribute(hgemm<false, false>, cudaFuncAttributeMaxDynamicSharedMemorySize, HG_SMEM);

    float *p_x, *p_qkv, *p_att, *p_tmp, *p_x1, *p_h2, *p_x2, *p_f1p;
    cudaGetSymbolAddress((void**)&p_x,   g_x);
    cudaGetSymbolAddress((void**)&p_qkv, g_qkv);
    cudaGetSymbolAddress((void**)&p_att, g_att);
    cudaGetSymbolAddress((void**)&p_tmp, g_tmp);
    cudaGetSymbolAddress((void**)&p_x1,  g_x1);
    cudaGetSymbolAddress((void**)&p_h2,  g_h2);
    cudaGetSymbolAddress((void**)&p_x2,  g_x2);
    cudaGetSymbolAddress((void**)&p_f1p, g_f1p);

    k_tile<<<4096, 256>>>(t);
    k_conv1<<<4096, 256>>>(conv1_w, conv1_b);
    k_conv2<<<4096, 288, 65664>>>(conv2_w, conv2_b);
    k_expand<<<2048, 256>>>(expand_w, expand_b);
    k_gattn<<<4096, 192, 58112>>>(mha_wqkv, mha_bqkv, mha_wo, mha_bo, ln1_w, ln1_b);

    // qkv: (4096,2048) @ (6144,2048)^T
    hgemm<false, true><<<dim3(48, 32, 1), 256, HG_SMEM>>>(p_x, enc_wqkv, enc_bqkv, p_qkv,
                                                          6144, 2048, 2048, 0);
    k_encattn<<<4096, 128>>>();
    hgemm<false, true><<<dim3(16, 32, 1), 256, HG_SMEM>>>(p_att, enc_wo, enc_bo, p_tmp,
                                                          2048, 2048, 2048, 0);
    k_ln2048<<<4096, 256>>>(p_x, p_tmp, enc_ln1w, enc_ln1b, p_x1);
    hgemm<true, true><<<dim3(16, 32, 1), 256, HG_SMEM>>>(p_x1, enc_w1, enc_b1, p_h2,
                                                         2048, 2048, 2048, 0);
    hgemm<false, true><<<dim3(16, 32, 1), 256, HG_SMEM>>>(p_h2, enc_w2, enc_b2, p_tmp,
                                                          2048, 2048, 2048, 0);
    k_ln2048<<<4096, 256>>>(p_x1, p_tmp, enc_ln2w, enc_ln2b, p_x2);

    // f1: (256,32768) @ (512,32768)^T, split-K 32
    hgemm<false, false><<<dim3(4, 2, 32), 256, HG_SMEM>>>(p_x2, f1_w, nullptr, p_f1p,
                                                          512, 32768, 1024, 256 * 512);
    k_f1red<<<512, 256>>>(f1_b);
    k_f2<<<256, 128>>>(f2_w, f2_b);
    k_f3<<<256, 32>>>(f3_w, f3_b, out);
}